// round 2
// baseline (speedup 1.0000x reference)
#include <cuda_runtime.h>
#include <cuda_bf16.h>
#include <cstdint>

#define NEG_SLOPE 0.01f
#define LN_EPS    1e-5f

#define DN 128
#define DE 64
#define DG 32
#define DO 128
#define MAXN 50000

// ---------------- scratch (device globals; no allocation allowed) ----------
__device__ __align__(16) float g_xw1 [MAXN * DO];   // x @ Wx
__device__ __align__(16) float g_xw2 [MAXN * DO];   // x @ W2a_x + b2a
__device__ __align__(16) float g_sums[MAXN * DO];   // scatter accumulator (LN output)
__device__ __align__(16) float g_cnt [MAXN];
__device__ __align__(16) float g_c1  [DO];          // u @ Wu + b1a

// ---------------- kernel 0: c1 = u @ Wu + b1a ------------------------------
__global__ void c1_kernel(const float* __restrict__ W1a,
                          const float* __restrict__ b1a,
                          const float* __restrict__ u) {
    int j = threadIdx.x;            // 128 threads
    float acc = b1a[j];
#pragma unroll
    for (int k = 0; k < DG; ++k)
        acc += u[k] * W1a[(DN + DE + k) * DO + j];
    g_c1[j] = acc;
}

// ---------------- kernel 1: zero scatter buffers ---------------------------
__global__ void zero_kernel(int n_sum, int n_cnt) {
    int i      = blockIdx.x * blockDim.x + threadIdx.x;
    int stride = gridDim.x * blockDim.x;
    for (int idx = i; idx < n_sum; idx += stride) g_sums[idx] = 0.0f;
    for (int idx = i; idx < n_cnt; idx += stride) g_cnt[idx]  = 0.0f;
}

// ---------------- kernel 2: per-node precompute ----------------------------
// xw1 = x @ Wx            (W1a rows 0..127)
// xw2 = x @ W2a_x + b2a   (W2a rows 0..127)
__global__ void precompute_kernel(const float* __restrict__ x,
                                  const float* __restrict__ W1a,
                                  const float* __restrict__ W2a,
                                  const float* __restrict__ b2a,
                                  int N) {
    extern __shared__ float sm[];
    float* Wx_s  = sm;                       // DN*DO
    float* W2_s  = sm + DN * DO;             // DN*DO
    float* b2a_s = sm + 2 * DN * DO;         // DO
    float* xs    = sm + 2 * DN * DO + DO;    // 8 warps * DN

    for (int idx = threadIdx.x; idx < DN * DO; idx += blockDim.x) {
        Wx_s[idx] = W1a[idx];
        W2_s[idx] = W2a[idx];
    }
    if (threadIdx.x < DO) b2a_s[threadIdx.x] = b2a[threadIdx.x];
    __syncthreads();

    int lane  = threadIdx.x & 31;
    int warp  = threadIdx.x >> 5;
    int gw    = blockIdx.x * (blockDim.x >> 5) + warp;
    int nwtot = gridDim.x * (blockDim.x >> 5);
    float* myxs = xs + warp * DN;

    for (int node = gw; node < N; node += nwtot) {
        float4 xr = reinterpret_cast<const float4*>(x)[node * (DN / 4) + lane];
        reinterpret_cast<float4*>(myxs)[lane] = xr;
        __syncwarp();

        float4 a1 = make_float4(0.f, 0.f, 0.f, 0.f);
        float4 a2 = reinterpret_cast<float4*>(b2a_s)[lane];
#pragma unroll 16
        for (int k = 0; k < DN; ++k) {
            float  xk = myxs[k];
            float4 w1 = reinterpret_cast<float4*>(Wx_s + k * DO)[lane];
            float4 w2 = reinterpret_cast<float4*>(W2_s + k * DO)[lane];
            a1.x += xk * w1.x; a1.y += xk * w1.y; a1.z += xk * w1.z; a1.w += xk * w1.w;
            a2.x += xk * w2.x; a2.y += xk * w2.y; a2.z += xk * w2.z; a2.w += xk * w2.w;
        }
        reinterpret_cast<float4*>(g_xw1)[node * (DO / 4) + lane] = a1;
        reinterpret_cast<float4*>(g_xw2)[node * (DO / 4) + lane] = a2;
        __syncwarp();
    }
}

// ---------------- kernel 3: edge phase -------------------------------------
// h = xw1[src] + c1 + edge_attr @ We ; LeakyReLU ; LayerNorm(g1,be1)
// scatter-add h_ln into g_sums[dest], count into g_cnt[dest]
__global__ void edge_kernel(const int*   __restrict__ ei,
                            const float* __restrict__ edge_attr,
                            const float* __restrict__ W1a,
                            const float* __restrict__ g1,
                            const float* __restrict__ be1,
                            int E) {
    extern __shared__ float sm[];
    float* We_s  = sm;                         // DE*DO = 8192
    float* c1_s  = sm + DE * DO;               // 128
    float* g1_s  = c1_s + DO;                  // 128
    float* be1_s = g1_s + DO;                  // 128
    float* eas   = be1_s + DO;                 // 8 warps * DE

    for (int idx = threadIdx.x; idx < DE * DO; idx += blockDim.x)
        We_s[idx] = W1a[DN * DO + idx];
    if (threadIdx.x < DO) {
        c1_s [threadIdx.x] = g_c1[threadIdx.x];
        g1_s [threadIdx.x] = g1  [threadIdx.x];
        be1_s[threadIdx.x] = be1 [threadIdx.x];
    }
    __syncthreads();

    int lane  = threadIdx.x & 31;
    int warp  = threadIdx.x >> 5;
    int gw    = blockIdx.x * (blockDim.x >> 5) + warp;
    int nwtot = gridDim.x * (blockDim.x >> 5);
    float* myea = eas + warp * DE;

    for (int e = gw; e < E; e += nwtot) {
        int src = ei[e];
        int dst = ei[E + e];

        float2 eav = reinterpret_cast<const float2*>(edge_attr)[e * (DE / 2) + lane];
        reinterpret_cast<float2*>(myea)[lane] = eav;

        float4 acc = reinterpret_cast<const float4*>(g_xw1)[src * (DO / 4) + lane];
        float4 cc  = reinterpret_cast<float4*>(c1_s)[lane];
        acc.x += cc.x; acc.y += cc.y; acc.z += cc.z; acc.w += cc.w;
        __syncwarp();

#pragma unroll
        for (int k = 0; k < DE; ++k) {
            float  ak = myea[k];
            float4 w  = reinterpret_cast<float4*>(We_s + k * DO)[lane];
            acc.x += ak * w.x; acc.y += ak * w.y; acc.z += ak * w.z; acc.w += ak * w.w;
        }

        // LeakyReLU
        acc.x = acc.x >= 0.f ? acc.x : NEG_SLOPE * acc.x;
        acc.y = acc.y >= 0.f ? acc.y : NEG_SLOPE * acc.y;
        acc.z = acc.z >= 0.f ? acc.z : NEG_SLOPE * acc.z;
        acc.w = acc.w >= 0.f ? acc.w : NEG_SLOPE * acc.w;

        // LayerNorm over 128 (4 per lane)
        float s = acc.x + acc.y + acc.z + acc.w;
#pragma unroll
        for (int o = 16; o > 0; o >>= 1) s += __shfl_xor_sync(0xffffffffu, s, o);
        float mu = s * (1.0f / DO);
        float dx = acc.x - mu, dy = acc.y - mu, dz = acc.z - mu, dw = acc.w - mu;
        float v = dx * dx + dy * dy + dz * dz + dw * dw;
#pragma unroll
        for (int o = 16; o > 0; o >>= 1) v += __shfl_xor_sync(0xffffffffu, v, o);
        float inv = rsqrtf(v * (1.0f / DO) + LN_EPS);

        float4 gg = reinterpret_cast<float4*>(g1_s)[lane];
        float4 bb = reinterpret_cast<float4*>(be1_s)[lane];
        float hx = dx * inv * gg.x + bb.x;
        float hy = dy * inv * gg.y + bb.y;
        float hz = dz * inv * gg.z + bb.z;
        float hw = dw * inv * gg.w + bb.w;

        float* p = g_sums + (size_t)dst * DO + lane * 4;
        asm volatile("red.global.add.v4.f32 [%0], {%1, %2, %3, %4};"
                     :: "l"(p), "f"(hx), "f"(hy), "f"(hz), "f"(hw) : "memory");
        if (lane == 0) atomicAdd(g_cnt + dst, 1.0f);
        __syncwarp();
    }
}

// ---------------- kernel 4: node phase -------------------------------------
// agg = (cnt>0) ? (sums/cnt) @ W1b + b1b : 0
// t   = xw2 + agg @ W2a_agg ; LeakyReLU ; LN(g2,be2) ; out = t @ W2b + b2b
__global__ void node_kernel(const float* __restrict__ W1b,
                            const float* __restrict__ b1b,
                            const float* __restrict__ W2a,
                            const float* __restrict__ g2,
                            const float* __restrict__ be2,
                            const float* __restrict__ W2b,
                            const float* __restrict__ b2b,
                            float* __restrict__ out,
                            int N) {
    extern __shared__ float sm[];
    float* W1b_s = sm;                         // DO*DO
    float* W2g_s = sm + DO * DO;               // DO*DO (agg part of W2a)
    float* W2b_s = sm + 2 * DO * DO;           // DO*DO
    float* b1b_s = sm + 3 * DO * DO;           // DO
    float* g2_s  = b1b_s + DO;
    float* be2_s = g2_s + DO;
    float* b2b_s = be2_s + DO;
    float* stg   = b2b_s + DO;                 // 8 warps * DO

    for (int idx = threadIdx.x; idx < DO * DO; idx += blockDim.x) {
        W1b_s[idx] = W1b[idx];
        W2g_s[idx] = W2a[DN * DO + idx];
        W2b_s[idx] = W2b[idx];
    }
    if (threadIdx.x < DO) {
        b1b_s[threadIdx.x] = b1b[threadIdx.x];
        g2_s [threadIdx.x] = g2 [threadIdx.x];
        be2_s[threadIdx.x] = be2[threadIdx.x];
        b2b_s[threadIdx.x] = b2b[threadIdx.x];
    }
    __syncthreads();

    int lane  = threadIdx.x & 31;
    int warp  = threadIdx.x >> 5;
    int gw    = blockIdx.x * (blockDim.x >> 5) + warp;
    int nwtot = gridDim.x * (blockDim.x >> 5);
    float* mys = stg + warp * DO;

    for (int node = gw; node < N; node += nwtot) {
        float cnt = g_cnt[node];
        float4 aggv;
        if (cnt > 0.f) {
            float4 sv = reinterpret_cast<float4*>(g_sums)[node * (DO / 4) + lane];
            float ic = 1.0f / cnt;
            sv.x *= ic; sv.y *= ic; sv.z *= ic; sv.w *= ic;
            reinterpret_cast<float4*>(mys)[lane] = sv;
            __syncwarp();
            float4 a = reinterpret_cast<float4*>(b1b_s)[lane];
#pragma unroll 16
            for (int k = 0; k < DO; ++k) {
                float  mk = mys[k];
                float4 w  = reinterpret_cast<float4*>(W1b_s + k * DO)[lane];
                a.x += mk * w.x; a.y += mk * w.y; a.z += mk * w.z; a.w += mk * w.w;
            }
            aggv = a;
            __syncwarp();
        } else {
            aggv = make_float4(0.f, 0.f, 0.f, 0.f);
        }

        reinterpret_cast<float4*>(mys)[lane] = aggv;
        __syncwarp();
        float4 t = reinterpret_cast<float4*>(g_xw2)[node * (DO / 4) + lane];
#pragma unroll 16
        for (int k = 0; k < DO; ++k) {
            float  ak = mys[k];
            float4 w  = reinterpret_cast<float4*>(W2g_s + k * DO)[lane];
            t.x += ak * w.x; t.y += ak * w.y; t.z += ak * w.z; t.w += ak * w.w;
        }

        t.x = t.x >= 0.f ? t.x : NEG_SLOPE * t.x;
        t.y = t.y >= 0.f ? t.y : NEG_SLOPE * t.y;
        t.z = t.z >= 0.f ? t.z : NEG_SLOPE * t.z;
        t.w = t.w >= 0.f ? t.w : NEG_SLOPE * t.w;

        float s = t.x + t.y + t.z + t.w;
#pragma unroll
        for (int o = 16; o > 0; o >>= 1) s += __shfl_xor_sync(0xffffffffu, s, o);
        float mu = s * (1.0f / DO);
        float dx = t.x - mu, dy = t.y - mu, dz = t.z - mu, dw = t.w - mu;
        float v = dx * dx + dy * dy + dz * dz + dw * dw;
#pragma unroll
        for (int o = 16; o > 0; o >>= 1) v += __shfl_xor_sync(0xffffffffu, v, o);
        float inv = rsqrtf(v * (1.0f / DO) + LN_EPS);

        float4 gg = reinterpret_cast<float4*>(g2_s)[lane];
        float4 bb = reinterpret_cast<float4*>(be2_s)[lane];
        float4 tn;
        tn.x = dx * inv * gg.x + bb.x;
        tn.y = dy * inv * gg.y + bb.y;
        tn.z = dz * inv * gg.z + bb.z;
        tn.w = dw * inv * gg.w + bb.w;

        __syncwarp();
        reinterpret_cast<float4*>(mys)[lane] = tn;
        __syncwarp();

        float4 o4 = reinterpret_cast<float4*>(b2b_s)[lane];
#pragma unroll 16
        for (int k = 0; k < DO; ++k) {
            float  tk = mys[k];
            float4 w  = reinterpret_cast<float4*>(W2b_s + k * DO)[lane];
            o4.x += tk * w.x; o4.y += tk * w.y; o4.z += tk * w.z; o4.w += tk * w.w;
        }
        reinterpret_cast<float4*>(out)[node * (DO / 4) + lane] = o4;
        __syncwarp();
    }
}

// ---------------- launcher -------------------------------------------------
static bool g_attr_done = false;

extern "C" void kernel_launch(void* const* d_in, const int* in_sizes, int n_in,
                              void* d_out, int out_size) {
    const float* x   = (const float*)d_in[0];
    const int*   ei  = (const int*)  d_in[1];
    const float* ea  = (const float*)d_in[2];
    const float* u   = (const float*)d_in[3];
    // d_in[4] = batch (unused: single graph)
    const float* W1a = (const float*)d_in[5];
    const float* b1a = (const float*)d_in[6];
    const float* g1  = (const float*)d_in[7];
    const float* be1 = (const float*)d_in[8];
    const float* W1b = (const float*)d_in[9];
    const float* b1b = (const float*)d_in[10];
    const float* W2a = (const float*)d_in[11];
    const float* b2a = (const float*)d_in[12];
    const float* g2  = (const float*)d_in[13];
    const float* be2 = (const float*)d_in[14];
    const float* W2b = (const float*)d_in[15];
    const float* b2b = (const float*)d_in[16];
    float* out = (float*)d_out;

    int N = in_sizes[0] / DN;
    int E = in_sizes[2] / DE;

    const int PRE_SMEM  = (2 * DN * DO + DO + 8 * DN) * (int)sizeof(float);      // ~132.5 KB
    const int EDGE_SMEM = (DE * DO + 3 * DO + 8 * DE) * (int)sizeof(float);      // ~35.5 KB
    const int NODE_SMEM = (3 * DO * DO + 4 * DO + 8 * DO) * (int)sizeof(float);  // ~198 KB

    if (!g_attr_done) {
        cudaFuncSetAttribute(precompute_kernel, cudaFuncAttributeMaxDynamicSharedMemorySize, PRE_SMEM);
        cudaFuncSetAttribute(edge_kernel,       cudaFuncAttributeMaxDynamicSharedMemorySize, EDGE_SMEM);
        cudaFuncSetAttribute(node_kernel,       cudaFuncAttributeMaxDynamicSharedMemorySize, NODE_SMEM);
        g_attr_done = true;
    }

    c1_kernel<<<1, 128>>>(W1a, b1a, u);
    zero_kernel<<<256, 256>>>(N * DO, N);
    precompute_kernel<<<148, 256, PRE_SMEM>>>(x, W1a, W2a, b2a, N);
    edge_kernel<<<888, 256, EDGE_SMEM>>>(ei, ea, W1a, g1, be1, E);
    node_kernel<<<148, 256, NODE_SMEM>>>(W1b, b1b, W2a, g2, be2, W2b, b2b, out, N);
}

// round 3
// speedup vs baseline: 1.9678x; 1.9678x over previous
#include <cuda_runtime.h>
#include <cuda_bf16.h>
#include <cstdint>

#define NEG_SLOPE 0.01f
#define LN_EPS    1e-5f

#define DN 128
#define DE 64
#define DG 32
#define DO 128
#define MAXN 50000
#define EPB 8          // edges per warp-pass
#define NPB 4          // nodes per warp-pass

typedef unsigned long long ull;

// ---------------- f32x2 packed-FMA helpers (sm_103a) -----------------------
__device__ __forceinline__ ull ffma2(ull a, ull b, ull c) {
    ull d;
    asm("fma.rn.f32x2 %0, %1, %2, %3;" : "=l"(d) : "l"(a), "l"(b), "l"(c));
    return d;
}
__device__ __forceinline__ ull pack2(float lo, float hi) {
    ull d;
    asm("mov.b64 %0, {%1, %2};" : "=l"(d) : "f"(lo), "f"(hi));
    return d;
}
__device__ __forceinline__ void unpack2(ull v, float& lo, float& hi) {
    asm("mov.b64 {%0, %1}, %2;" : "=f"(lo), "=f"(hi) : "l"(v));
}

// ---------------- scratch (device globals) ---------------------------------
__device__ __align__(16) float g_xw1 [MAXN * DO];   // x @ Wx  ; reused as agg by node_a
__device__ __align__(16) float g_xw2 [MAXN * DO];   // x @ W2a_x + b2a
__device__ __align__(16) float g_sums[MAXN * DO];   // scatter accumulator (LN output)
__device__ __align__(16) float g_cnt [MAXN];
__device__ __align__(16) float g_c1  [DO];          // u @ Wu + b1a

// ---------------- kernel 0: c1 = u @ Wu + b1a ------------------------------
__global__ void c1_kernel(const float* __restrict__ W1a,
                          const float* __restrict__ b1a,
                          const float* __restrict__ u) {
    int j = threadIdx.x;            // 128 threads
    float acc = b1a[j];
#pragma unroll
    for (int k = 0; k < DG; ++k)
        acc += u[k] * W1a[(DN + DE + k) * DO + j];
    g_c1[j] = acc;
}

// ---------------- kernel 1: zero scatter buffers ---------------------------
__global__ void zero_kernel(int n_sum, int n_cnt) {
    int i      = blockIdx.x * blockDim.x + threadIdx.x;
    int stride = gridDim.x * blockDim.x;
    for (int idx = i; idx < n_sum; idx += stride) g_sums[idx] = 0.0f;
    for (int idx = i; idx < n_cnt; idx += stride) g_cnt[idx]  = 0.0f;
}

// ---------------- kernel 2: per-node precompute (NPB-blocked) --------------
// xw1 = x @ Wx ; xw2 = x @ W2a_x + b2a
__global__ void __launch_bounds__(512) precompute_kernel(
        const float* __restrict__ x,
        const float* __restrict__ W1a,
        const float* __restrict__ W2a,
        const float* __restrict__ b2a,
        int N) {
    extern __shared__ float sm[];
    float*  Wx_s   = sm;                       // DN*DO
    float*  W2_s   = sm + DN * DO;             // DN*DO
    float*  b2a_s  = sm + 2 * DN * DO;         // DO
    float2* xd_all = (float2*)(b2a_s + DO);    // 16 warps * NPB * DN dup-f2

    for (int idx = threadIdx.x; idx < DN * DO; idx += blockDim.x) {
        Wx_s[idx] = W1a[idx];
        W2_s[idx] = W2a[idx];
    }
    if (threadIdx.x < DO) b2a_s[threadIdx.x] = b2a[threadIdx.x];
    __syncthreads();

    int lane = threadIdx.x & 31;
    int warp = threadIdx.x >> 5;
    float2*    xd  = xd_all + warp * (NPB * DN);
    const ull* xdq = (const ull*)xd;
    int gw = blockIdx.x * (blockDim.x >> 5) + warp;
    int nw = gridDim.x * (blockDim.x >> 5);

    float4 b4 = reinterpret_cast<float4*>(b2a_s)[lane];
    ull b2lo = pack2(b4.x, b4.y), b2hi = pack2(b4.z, b4.w);

    for (int base = gw * NPB; base < N; base += nw * NPB) {
        int ne = min(NPB, N - base);
        __syncwarp();
#pragma unroll
        for (int n = 0; n < NPB; ++n) {
            int node = (n < ne) ? base + n : base;
            float4 xr = reinterpret_cast<const float4*>(x)[(size_t)node * (DN / 4) + lane];
            xd[n * DN + 4 * lane + 0] = make_float2(xr.x, xr.x);
            xd[n * DN + 4 * lane + 1] = make_float2(xr.y, xr.y);
            xd[n * DN + 4 * lane + 2] = make_float2(xr.z, xr.z);
            xd[n * DN + 4 * lane + 3] = make_float2(xr.w, xr.w);
        }
        __syncwarp();

        ull a1lo[NPB], a1hi[NPB], a2lo[NPB], a2hi[NPB];
#pragma unroll
        for (int n = 0; n < NPB; ++n) {
            a1lo[n] = 0ull; a1hi[n] = 0ull;
            a2lo[n] = b2lo; a2hi[n] = b2hi;
        }
#pragma unroll 2
        for (int k = 0; k < DN; ++k) {
            float4 w1 = reinterpret_cast<float4*>(Wx_s + k * DO)[lane];
            float4 w2 = reinterpret_cast<float4*>(W2_s + k * DO)[lane];
            ull w1lo = pack2(w1.x, w1.y), w1hi = pack2(w1.z, w1.w);
            ull w2lo = pack2(w2.x, w2.y), w2hi = pack2(w2.z, w2.w);
#pragma unroll
            for (int n = 0; n < NPB; ++n) {
                ull a = xdq[n * DN + k];
                a1lo[n] = ffma2(w1lo, a, a1lo[n]);
                a1hi[n] = ffma2(w1hi, a, a1hi[n]);
                a2lo[n] = ffma2(w2lo, a, a2lo[n]);
                a2hi[n] = ffma2(w2hi, a, a2hi[n]);
            }
        }
#pragma unroll
        for (int n = 0; n < NPB; ++n) {
            if (n < ne) {
                int node = base + n;
                float4 o1, o2;
                unpack2(a1lo[n], o1.x, o1.y); unpack2(a1hi[n], o1.z, o1.w);
                unpack2(a2lo[n], o2.x, o2.y); unpack2(a2hi[n], o2.z, o2.w);
                reinterpret_cast<float4*>(g_xw1)[(size_t)node * (DO / 4) + lane] = o1;
                reinterpret_cast<float4*>(g_xw2)[(size_t)node * (DO / 4) + lane] = o2;
            }
        }
    }
}

// ---------------- kernel 3: edge phase (EPB-blocked) -----------------------
// h = xw1[src] + c1 + edge_attr @ We ; LeakyReLU ; LN(g1,be1) ; scatter-add
__global__ void __launch_bounds__(256) edge_kernel(
        const int*   __restrict__ ei,
        const float* __restrict__ edge_attr,
        const float* __restrict__ W1a,
        const float* __restrict__ g1,
        const float* __restrict__ be1,
        int E) {
    extern __shared__ float sm[];
    float*  We_s    = sm;                      // DE*DO
    float*  c1_s    = sm + DE * DO;
    float*  g1_s    = c1_s + DO;
    float*  be1_s   = g1_s + DO;
    float2* ead_all = (float2*)(be1_s + DO);   // 8 warps * EPB * DE dup-f2

    for (int idx = threadIdx.x; idx < DE * DO; idx += blockDim.x)
        We_s[idx] = W1a[DN * DO + idx];
    if (threadIdx.x < DO) {
        c1_s [threadIdx.x] = g_c1[threadIdx.x];
        g1_s [threadIdx.x] = g1  [threadIdx.x];
        be1_s[threadIdx.x] = be1 [threadIdx.x];
    }
    __syncthreads();

    int lane = threadIdx.x & 31;
    int warp = threadIdx.x >> 5;
    float2*    ead  = ead_all + warp * (EPB * DE);
    const ull* eadq = (const ull*)ead;
    int gw = blockIdx.x * 8 + warp;
    int nw = gridDim.x * 8;

    float4 cc = reinterpret_cast<float4*>(c1_s )[lane];
    float4 gg = reinterpret_cast<float4*>(g1_s )[lane];
    float4 bb = reinterpret_cast<float4*>(be1_s)[lane];

    for (int base = gw * EPB; base < E; base += nw * EPB) {
        int ne = min(EPB, E - base);
        int dsts[EPB];
        ull alo[EPB], ahi[EPB];
        __syncwarp();
#pragma unroll
        for (int e = 0; e < EPB; ++e) {
            int ii  = (e < ne) ? base + e : base;
            int src = ei[ii];
            dsts[e] = ei[E + ii];
            float2 v = reinterpret_cast<const float2*>(edge_attr)[(size_t)ii * (DE / 2) + lane];
            ead[e * DE + 2 * lane    ] = make_float2(v.x, v.x);
            ead[e * DE + 2 * lane + 1] = make_float2(v.y, v.y);
            float4 a = reinterpret_cast<const float4*>(g_xw1)[(size_t)src * (DO / 4) + lane];
            alo[e] = pack2(a.x + cc.x, a.y + cc.y);
            ahi[e] = pack2(a.z + cc.z, a.w + cc.w);
        }
        __syncwarp();

#pragma unroll 4
        for (int k = 0; k < DE; ++k) {
            float4 w = reinterpret_cast<float4*>(We_s + k * DO)[lane];
            ull wlo = pack2(w.x, w.y), whi = pack2(w.z, w.w);
#pragma unroll
            for (int e = 0; e < EPB; ++e) {
                ull a = eadq[e * DE + k];
                alo[e] = ffma2(wlo, a, alo[e]);
                ahi[e] = ffma2(whi, a, ahi[e]);
            }
        }

#pragma unroll
        for (int e = 0; e < EPB; ++e) {
            if (e < ne) {
                float x0, x1, x2, x3;
                unpack2(alo[e], x0, x1); unpack2(ahi[e], x2, x3);
                x0 = x0 >= 0.f ? x0 : NEG_SLOPE * x0;
                x1 = x1 >= 0.f ? x1 : NEG_SLOPE * x1;
                x2 = x2 >= 0.f ? x2 : NEG_SLOPE * x2;
                x3 = x3 >= 0.f ? x3 : NEG_SLOPE * x3;

                float s = x0 + x1 + x2 + x3;
#pragma unroll
                for (int o = 16; o > 0; o >>= 1) s += __shfl_xor_sync(0xffffffffu, s, o);
                float mu = s * (1.0f / DO);
                float d0 = x0 - mu, d1 = x1 - mu, d2 = x2 - mu, d3 = x3 - mu;
                float vv = d0 * d0 + d1 * d1 + d2 * d2 + d3 * d3;
#pragma unroll
                for (int o = 16; o > 0; o >>= 1) vv += __shfl_xor_sync(0xffffffffu, vv, o);
                float inv = rsqrtf(vv * (1.0f / DO) + LN_EPS);

                float h0 = d0 * inv * gg.x + bb.x;
                float h1 = d1 * inv * gg.y + bb.y;
                float h2 = d2 * inv * gg.z + bb.z;
                float h3 = d3 * inv * gg.w + bb.w;

                float* p = g_sums + (size_t)dsts[e] * DO + lane * 4;
                asm volatile("red.global.add.v4.f32 [%0], {%1, %2, %3, %4};"
                             :: "l"(p), "f"(h0), "f"(h1), "f"(h2), "f"(h3) : "memory");
            }
        }
        if (lane == 0) {
#pragma unroll
            for (int e = 0; e < EPB; ++e)
                if (e < ne) atomicAdd(g_cnt + dsts[e], 1.0f);
        }
    }
}

// ---------------- kernel 4a: agg = (cnt>0) ? (sums/cnt)@W1b + b1b : 0 ------
// writes agg into g_xw1 (xw1 is consumed; reuse)
__global__ void __launch_bounds__(256) node_a_kernel(
        const float* __restrict__ W1b,
        const float* __restrict__ b1b,
        int N) {
    extern __shared__ float sm[];
    float*  W1b_s  = sm;                       // DO*DO
    float*  b1b_s  = sm + DO * DO;             // DO
    float2* st_all = (float2*)(b1b_s + DO);    // 8 warps * NPB * DO dup-f2

    for (int idx = threadIdx.x; idx < DO * DO; idx += blockDim.x)
        W1b_s[idx] = W1b[idx];
    if (threadIdx.x < DO) b1b_s[threadIdx.x] = b1b[threadIdx.x];
    __syncthreads();

    int lane = threadIdx.x & 31;
    int warp = threadIdx.x >> 5;
    float2*    st  = st_all + warp * (NPB * DO);
    const ull* stq = (const ull*)st;
    int gw = blockIdx.x * 8 + warp;
    int nw = gridDim.x * 8;

    float4 b4 = reinterpret_cast<float4*>(b1b_s)[lane];
    ull blo = pack2(b4.x, b4.y), bhi = pack2(b4.z, b4.w);

    for (int base = gw * NPB; base < N; base += nw * NPB) {
        int ne = min(NPB, N - base);
        float cnts[NPB];
        __syncwarp();
#pragma unroll
        for (int n = 0; n < NPB; ++n) {
            int node = (n < ne) ? base + n : base;
            float c = g_cnt[node];
            cnts[n] = c;
            float ic = c > 0.f ? (1.0f / c) : 0.f;
            float4 sv = reinterpret_cast<float4*>(g_sums)[(size_t)node * (DO / 4) + lane];
            st[n * DO + 4 * lane + 0] = make_float2(sv.x * ic, sv.x * ic);
            st[n * DO + 4 * lane + 1] = make_float2(sv.y * ic, sv.y * ic);
            st[n * DO + 4 * lane + 2] = make_float2(sv.z * ic, sv.z * ic);
            st[n * DO + 4 * lane + 3] = make_float2(sv.w * ic, sv.w * ic);
        }
        __syncwarp();

        ull alo[NPB], ahi[NPB];
#pragma unroll
        for (int n = 0; n < NPB; ++n) { alo[n] = blo; ahi[n] = bhi; }
#pragma unroll 2
        for (int k = 0; k < DO; ++k) {
            float4 w = reinterpret_cast<float4*>(W1b_s + k * DO)[lane];
            ull wlo = pack2(w.x, w.y), whi = pack2(w.z, w.w);
#pragma unroll
            for (int n = 0; n < NPB; ++n) {
                ull a = stq[n * DO + k];
                alo[n] = ffma2(wlo, a, alo[n]);
                ahi[n] = ffma2(whi, a, ahi[n]);
            }
        }
#pragma unroll
        for (int n = 0; n < NPB; ++n) {
            if (n < ne) {
                int node = base + n;
                float4 o;
                if (cnts[n] > 0.f) {
                    unpack2(alo[n], o.x, o.y); unpack2(ahi[n], o.z, o.w);
                } else {
                    o = make_float4(0.f, 0.f, 0.f, 0.f);
                }
                reinterpret_cast<float4*>(g_xw1)[(size_t)node * (DO / 4) + lane] = o;
            }
        }
    }
}

// ---------------- kernel 4b: final MLP -------------------------------------
// t = xw2 + agg@W2a_agg ; LeakyReLU ; LN(g2,be2) ; out = t@W2b + b2b
__global__ void __launch_bounds__(512) node_b_kernel(
        const float* __restrict__ W2a,
        const float* __restrict__ g2,
        const float* __restrict__ be2,
        const float* __restrict__ W2b,
        const float* __restrict__ b2b,
        float* __restrict__ out,
        int N) {
    extern __shared__ float sm[];
    float*  W2g_s  = sm;                       // DO*DO (agg part of W2a)
    float*  W2b_s  = sm + DO * DO;             // DO*DO
    float*  g2_s   = sm + 2 * DO * DO;         // DO
    float*  be2_s  = g2_s + DO;
    float*  b2b_s  = be2_s + DO;
    float2* st_all = (float2*)(b2b_s + DO);    // 16 warps * NPB * DO dup-f2

    for (int idx = threadIdx.x; idx < DO * DO; idx += blockDim.x) {
        W2g_s[idx] = W2a[DN * DO + idx];
        W2b_s[idx] = W2b[idx];
    }
    if (threadIdx.x < DO) {
        g2_s [threadIdx.x] = g2 [threadIdx.x];
        be2_s[threadIdx.x] = be2[threadIdx.x];
        b2b_s[threadIdx.x] = b2b[threadIdx.x];
    }
    __syncthreads();

    int lane = threadIdx.x & 31;
    int warp = threadIdx.x >> 5;
    float2*    st  = st_all + warp * (NPB * DO);
    const ull* stq = (const ull*)st;
    int gw = blockIdx.x * (blockDim.x >> 5) + warp;
    int nw = gridDim.x * (blockDim.x >> 5);

    float4 gg = reinterpret_cast<float4*>(g2_s )[lane];
    float4 be = reinterpret_cast<float4*>(be2_s)[lane];
    float4 b4 = reinterpret_cast<float4*>(b2b_s)[lane];
    ull blo = pack2(b4.x, b4.y), bhi = pack2(b4.z, b4.w);

    for (int base = gw * NPB; base < N; base += nw * NPB) {
        int ne = min(NPB, N - base);
        __syncwarp();
        ull tlo[NPB], thi[NPB];
#pragma unroll
        for (int n = 0; n < NPB; ++n) {
            int node = (n < ne) ? base + n : base;
            float4 av = reinterpret_cast<float4*>(g_xw1)[(size_t)node * (DO / 4) + lane];
            st[n * DO + 4 * lane + 0] = make_float2(av.x, av.x);
            st[n * DO + 4 * lane + 1] = make_float2(av.y, av.y);
            st[n * DO + 4 * lane + 2] = make_float2(av.z, av.z);
            st[n * DO + 4 * lane + 3] = make_float2(av.w, av.w);
            float4 t0 = reinterpret_cast<float4*>(g_xw2)[(size_t)node * (DO / 4) + lane];
            tlo[n] = pack2(t0.x, t0.y);
            thi[n] = pack2(t0.z, t0.w);
        }
        __syncwarp();

#pragma unroll 2
        for (int k = 0; k < DO; ++k) {
            float4 w = reinterpret_cast<float4*>(W2g_s + k * DO)[lane];
            ull wlo = pack2(w.x, w.y), whi = pack2(w.z, w.w);
#pragma unroll
            for (int n = 0; n < NPB; ++n) {
                ull a = stq[n * DO + k];
                tlo[n] = ffma2(wlo, a, tlo[n]);
                thi[n] = ffma2(whi, a, thi[n]);
            }
        }

        // LeakyReLU + LayerNorm per node; restage normalized vector (dup)
        __syncwarp();
#pragma unroll
        for (int n = 0; n < NPB; ++n) {
            float x0, x1, x2, x3;
            unpack2(tlo[n], x0, x1); unpack2(thi[n], x2, x3);
            x0 = x0 >= 0.f ? x0 : NEG_SLOPE * x0;
            x1 = x1 >= 0.f ? x1 : NEG_SLOPE * x1;
            x2 = x2 >= 0.f ? x2 : NEG_SLOPE * x2;
            x3 = x3 >= 0.f ? x3 : NEG_SLOPE * x3;

            float s = x0 + x1 + x2 + x3;
#pragma unroll
            for (int o = 16; o > 0; o >>= 1) s += __shfl_xor_sync(0xffffffffu, s, o);
            float mu = s * (1.0f / DO);
            float d0 = x0 - mu, d1 = x1 - mu, d2 = x2 - mu, d3 = x3 - mu;
            float vv = d0 * d0 + d1 * d1 + d2 * d2 + d3 * d3;
#pragma unroll
            for (int o = 16; o > 0; o >>= 1) vv += __shfl_xor_sync(0xffffffffu, vv, o);
            float inv = rsqrtf(vv * (1.0f / DO) + LN_EPS);

            float t0 = d0 * inv * gg.x + be.x;
            float t1 = d1 * inv * gg.y + be.y;
            float t2 = d2 * inv * gg.z + be.z;
            float t3 = d3 * inv * gg.w + be.w;
            st[n * DO + 4 * lane + 0] = make_float2(t0, t0);
            st[n * DO + 4 * lane + 1] = make_float2(t1, t1);
            st[n * DO + 4 * lane + 2] = make_float2(t2, t2);
            st[n * DO + 4 * lane + 3] = make_float2(t3, t3);
        }
        __syncwarp();

        ull olo[NPB], ohi[NPB];
#pragma unroll
        for (int n = 0; n < NPB; ++n) { olo[n] = blo; ohi[n] = bhi; }
#pragma unroll 2
        for (int k = 0; k < DO; ++k) {
            float4 w = reinterpret_cast<float4*>(W2b_s + k * DO)[lane];
            ull wlo = pack2(w.x, w.y), whi = pack2(w.z, w.w);
#pragma unroll
            for (int n = 0; n < NPB; ++n) {
                ull a = stq[n * DO + k];
                olo[n] = ffma2(wlo, a, olo[n]);
                ohi[n] = ffma2(whi, a, ohi[n]);
            }
        }
#pragma unroll
        for (int n = 0; n < NPB; ++n) {
            if (n < ne) {
                int node = base + n;
                float4 o;
                unpack2(olo[n], o.x, o.y); unpack2(ohi[n], o.z, o.w);
                reinterpret_cast<float4*>(out)[(size_t)node * (DO / 4) + lane] = o;
            }
        }
    }
}

// ---------------- launcher -------------------------------------------------
static bool g_attr_done = false;

extern "C" void kernel_launch(void* const* d_in, const int* in_sizes, int n_in,
                              void* d_out, int out_size) {
    const float* x   = (const float*)d_in[0];
    const int*   ei  = (const int*)  d_in[1];
    const float* ea  = (const float*)d_in[2];
    const float* u   = (const float*)d_in[3];
    // d_in[4] = batch (unused: single graph)
    const float* W1a = (const float*)d_in[5];
    const float* b1a = (const float*)d_in[6];
    const float* g1  = (const float*)d_in[7];
    const float* be1 = (const float*)d_in[8];
    const float* W1b = (const float*)d_in[9];
    const float* b1b = (const float*)d_in[10];
    const float* W2a = (const float*)d_in[11];
    const float* b2a = (const float*)d_in[12];
    const float* g2  = (const float*)d_in[13];
    const float* be2 = (const float*)d_in[14];
    const float* W2b = (const float*)d_in[15];
    const float* b2b = (const float*)d_in[16];
    float* out = (float*)d_out;

    int N = in_sizes[0] / DN;
    int E = in_sizes[2] / DE;

    const int PRE_SMEM  = (2 * DN * DO + DO) * 4 + 16 * NPB * DN * 8;   // 197120 B
    const int EDGE_SMEM = (DE * DO + 3 * DO) * 4 + 8 * EPB * DE * 8;    //  67072 B
    const int NA_SMEM   = (DO * DO + DO) * 4 + 8 * NPB * DO * 8;        //  98816 B
    const int NB_SMEM   = (2 * DO * DO + 3 * DO) * 4 + 16 * NPB * DO * 8; // 198144 B

    if (!g_attr_done) {
        cudaFuncSetAttribute(precompute_kernel, cudaFuncAttributeMaxDynamicSharedMemorySize, PRE_SMEM);
        cudaFuncSetAttribute(edge_kernel,       cudaFuncAttributeMaxDynamicSharedMemorySize, EDGE_SMEM);
        cudaFuncSetAttribute(node_a_kernel,     cudaFuncAttributeMaxDynamicSharedMemorySize, NA_SMEM);
        cudaFuncSetAttribute(node_b_kernel,     cudaFuncAttributeMaxDynamicSharedMemorySize, NB_SMEM);
        g_attr_done = true;
    }

    c1_kernel<<<1, 128>>>(W1a, b1a, u);
    zero_kernel<<<256, 256>>>(N * DO, N);
    precompute_kernel<<<148, 512, PRE_SMEM>>>(x, W1a, W2a, b2a, N);
    edge_kernel<<<3125, 256, EDGE_SMEM>>>(ei, ea, W1a, g1, be1, E);
    node_a_kernel<<<296, 256, NA_SMEM>>>(W1b, b1b, N);
    node_b_kernel<<<148, 512, NB_SMEM>>>(W2a, g2, be2, W2b, b2b, out, N);
}

// round 7
// speedup vs baseline: 2.4408x; 1.2404x over previous
#include <cuda_runtime.h>
#include <cuda_bf16.h>
#include <cstdint>

#define NEG_SLOPE 0.01f
#define LN_EPS    1e-5f

#define DN 128
#define DE 64
#define DG 32
#define DO 128
#define MAXN 50000
#define NPB 4          // nodes per warp-pass (node kernels)
#define PAD 72         // bf16 elems per smem row (64 data + 8 pad) = 144 B

typedef unsigned long long ull;

// ---------------- f32x2 packed-FMA helpers (node kernels) ------------------
__device__ __forceinline__ ull ffma2(ull a, ull b, ull c) {
    ull d;
    asm("fma.rn.f32x2 %0, %1, %2, %3;" : "=l"(d) : "l"(a), "l"(b), "l"(c));
    return d;
}
__device__ __forceinline__ ull pack2(float lo, float hi) {
    ull d;
    asm("mov.b64 %0, {%1, %2};" : "=l"(d) : "f"(lo), "f"(hi));
    return d;
}
__device__ __forceinline__ void unpack2(ull v, float& lo, float& hi) {
    asm("mov.b64 {%0, %1}, %2;" : "=f"(lo), "=f"(hi) : "l"(v));
}

// ---------------- scratch (device globals) ---------------------------------
__device__ __align__(16) float g_xw1 [MAXN * DO];
__device__ __align__(16) float g_xw2 [MAXN * DO];
__device__ __align__(16) float g_sums[MAXN * DO];
__device__ __align__(16) float g_cnt [MAXN];
__device__ __align__(16) float g_c1  [DO];

// ---------------- warp-MMA helper (baseline PTX, sm_80+) -------------------
__device__ __forceinline__ void mma16816(
        float& d0, float& d1, float& d2, float& d3,
        uint32_t a0, uint32_t a1, uint32_t a2, uint32_t a3,
        uint32_t b0, uint32_t b1) {
    asm volatile(
        "mma.sync.aligned.m16n8k16.row.col.f32.bf16.bf16.f32 "
        "{%0,%1,%2,%3}, {%4,%5,%6,%7}, {%8,%9}, {%0,%1,%2,%3};"
        : "+f"(d0), "+f"(d1), "+f"(d2), "+f"(d3)
        : "r"(a0), "r"(a1), "r"(a2), "r"(a3), "r"(b0), "r"(b1));
}
__device__ __forceinline__ uint32_t bfpair(float a, float b) {
    __nv_bfloat162 t = __floats2bfloat162_rn(a, b);   // x=a in low 16 bits
    return *reinterpret_cast<uint32_t*>(&t);
}

// ---------------- kernel 0: c1 = u @ Wu + b1a ------------------------------
__global__ void c1_kernel(const float* __restrict__ W1a,
                          const float* __restrict__ b1a,
                          const float* __restrict__ u) {
    int j = threadIdx.x;
    float acc = b1a[j];
#pragma unroll
    for (int k = 0; k < DG; ++k)
        acc += u[k] * W1a[(DN + DE + k) * DO + j];
    g_c1[j] = acc;
}

// ---------------- kernel 1: zero scatter buffers ---------------------------
__global__ void zero_kernel(int n_sum, int n_cnt) {
    int i      = blockIdx.x * blockDim.x + threadIdx.x;
    int stride = gridDim.x * blockDim.x;
    for (int idx = i; idx < n_sum; idx += stride) g_sums[idx] = 0.0f;
    for (int idx = i; idx < n_cnt; idx += stride) g_cnt[idx]  = 0.0f;
}

// ---------------- kernel 2: per-node precompute (R3, unchanged) ------------
__global__ void __launch_bounds__(512) precompute_kernel(
        const float* __restrict__ x,
        const float* __restrict__ W1a,
        const float* __restrict__ W2a,
        const float* __restrict__ b2a,
        int N) {
    extern __shared__ float sm[];
    float*  Wx_s   = sm;
    float*  W2_s   = sm + DN * DO;
    float*  b2a_s  = sm + 2 * DN * DO;
    float2* xd_all = (float2*)(b2a_s + DO);

    for (int idx = threadIdx.x; idx < DN * DO; idx += blockDim.x) {
        Wx_s[idx] = W1a[idx];
        W2_s[idx] = W2a[idx];
    }
    if (threadIdx.x < DO) b2a_s[threadIdx.x] = b2a[threadIdx.x];
    __syncthreads();

    int lane = threadIdx.x & 31;
    int warp = threadIdx.x >> 5;
    float2*    xd  = xd_all + warp * (NPB * DN);
    const ull* xdq = (const ull*)xd;
    int gw = blockIdx.x * (blockDim.x >> 5) + warp;
    int nw = gridDim.x * (blockDim.x >> 5);

    float4 b4 = reinterpret_cast<float4*>(b2a_s)[lane];
    ull b2lo = pack2(b4.x, b4.y), b2hi = pack2(b4.z, b4.w);

    for (int base = gw * NPB; base < N; base += nw * NPB) {
        int ne = min(NPB, N - base);
        __syncwarp();
#pragma unroll
        for (int n = 0; n < NPB; ++n) {
            int node = (n < ne) ? base + n : base;
            float4 xr = reinterpret_cast<const float4*>(x)[(size_t)node * (DN / 4) + lane];
            xd[n * DN + 4 * lane + 0] = make_float2(xr.x, xr.x);
            xd[n * DN + 4 * lane + 1] = make_float2(xr.y, xr.y);
            xd[n * DN + 4 * lane + 2] = make_float2(xr.z, xr.z);
            xd[n * DN + 4 * lane + 3] = make_float2(xr.w, xr.w);
        }
        __syncwarp();

        ull a1lo[NPB], a1hi[NPB], a2lo[NPB], a2hi[NPB];
#pragma unroll
        for (int n = 0; n < NPB; ++n) {
            a1lo[n] = 0ull; a1hi[n] = 0ull;
            a2lo[n] = b2lo; a2hi[n] = b2hi;
        }
#pragma unroll 2
        for (int k = 0; k < DN; ++k) {
            float4 w1 = reinterpret_cast<float4*>(Wx_s + k * DO)[lane];
            float4 w2 = reinterpret_cast<float4*>(W2_s + k * DO)[lane];
            ull w1lo = pack2(w1.x, w1.y), w1hi = pack2(w1.z, w1.w);
            ull w2lo = pack2(w2.x, w2.y), w2hi = pack2(w2.z, w2.w);
#pragma unroll
            for (int n = 0; n < NPB; ++n) {
                ull a = xdq[n * DN + k];
                a1lo[n] = ffma2(w1lo, a, a1lo[n]);
                a1hi[n] = ffma2(w1hi, a, a1hi[n]);
                a2lo[n] = ffma2(w2lo, a, a2lo[n]);
                a2hi[n] = ffma2(w2hi, a, a2hi[n]);
            }
        }
#pragma unroll
        for (int n = 0; n < NPB; ++n) {
            if (n < ne) {
                int node = base + n;
                float4 o1, o2;
                unpack2(a1lo[n], o1.x, o1.y); unpack2(a1hi[n], o1.z, o1.w);
                unpack2(a2lo[n], o2.x, o2.y); unpack2(a2hi[n], o2.z, o2.w);
                reinterpret_cast<float4*>(g_xw1)[(size_t)node * (DO / 4) + lane] = o1;
                reinterpret_cast<float4*>(g_xw2)[(size_t)node * (DO / 4) + lane] = o2;
            }
        }
    }
}

// ---------------- kernel 3: edge phase (mma.sync bf16 3-term) --------------
// Per tile of 128 edges: warp w computes edges [16w,16w+16) x all 128 outs.
// D = EA @ We ; h = D + xw1[src] + c1 ; LeakyReLU ; LN ; scatter-add.
__global__ void __launch_bounds__(256, 2) edge_kernel(
        const int*   __restrict__ ei,
        const float* __restrict__ ea,
        const float* __restrict__ W1a,
        const float* __restrict__ g1,
        const float* __restrict__ be1,
        int E) {
    extern __shared__ __align__(16) char smraw[];
    __nv_bfloat16* EAh = (__nv_bfloat16*)smraw;       // 128*PAD
    __nv_bfloat16* EAl = EAh + 128 * PAD;
    __nv_bfloat16* WTh = EAl + 128 * PAD;             // row o, 64 k
    __nv_bfloat16* WTl = WTh + 128 * PAD;
    float* c1s  = (float*)(WTl + 128 * PAD);          // 128
    float* g1s  = c1s + 128;
    float* be1s = g1s + 128;
    int*   sd   = (int*)(be1s + 128);                 // 128
    int*   dd   = sd + 128;

    int tid = threadIdx.x;

    // ---- one-time: stage W^T hi/lo (row = out, col = k), c1/g1/be1 ----
    for (int idx = tid; idx < DE * DO; idx += 256) {
        int k = idx >> 7, o = idx & 127;              // coalesced gmem read
        float v = W1a[(DN + k) * DO + o];
        __nv_bfloat16 h = __float2bfloat16(v);
        __nv_bfloat16 l = __float2bfloat16(v - __bfloat162float(h));
        WTh[o * PAD + k] = h;
        WTl[o * PAD + k] = l;
    }
    if (tid < 128) {
        c1s [tid] = g_c1[tid];
        g1s [tid] = g1  [tid];
        be1s[tid] = be1 [tid];
    }

    int warp = tid >> 5, lane = tid & 31;
    int R  = warp * 16;
    int qr = lane >> 2, qc = lane & 3;

    const float2* c1f2  = (const float2*)c1s;
    const float2* g1f2  = (const float2*)g1s;
    const float2* be1f2 = (const float2*)be1s;

    int ntiles = (E + 127) >> 7;
    for (int tile = blockIdx.x; tile < ntiles; tile += gridDim.x) {
        int base = tile << 7;
        __syncthreads();          // prior tile fully done everywhere

        // ---- stage EA tile: thread t -> edge t/2, k-half (t&1)*32 ----
        {
            int e  = tid >> 1;
            int kb = (tid & 1) * 32;
            int eg = base + e; if (eg >= E) eg = E - 1;
            const float4* s = (const float4*)(ea + (size_t)eg * DE + kb);
            ull* ph = (ull*)(EAh + e * PAD + kb);
            ull* pl = (ull*)(EAl + e * PAD + kb);
#pragma unroll
            for (int j = 0; j < 8; ++j) {
                float4 v = s[j];
                __nv_bfloat16 h0 = __float2bfloat16(v.x);
                __nv_bfloat16 h1 = __float2bfloat16(v.y);
                __nv_bfloat16 h2 = __float2bfloat16(v.z);
                __nv_bfloat16 h3 = __float2bfloat16(v.w);
                uint32_t hA = bfpair(v.x, v.y), hB = bfpair(v.z, v.w);
                uint32_t lA = bfpair(v.x - __bfloat162float(h0),
                                     v.y - __bfloat162float(h1));
                uint32_t lB = bfpair(v.z - __bfloat162float(h2),
                                     v.w - __bfloat162float(h3));
                ph[j] = (ull)hA | ((ull)hB << 32);
                pl[j] = (ull)lA | ((ull)lB << 32);
            }
            if (tid < 128) {
                int eg2 = base + tid; if (eg2 >= E) eg2 = E - 1;
                sd[tid] = ei[eg2];
                dd[tid] = ei[E + eg2];
            }
        }
        __syncthreads();

        // ---- MMA mainloop: D[16 x 128] per warp, 3-term bf16 split ----
        float d[16][4];
#pragma unroll
        for (int t = 0; t < 16; ++t) { d[t][0] = d[t][1] = d[t][2] = d[t][3] = 0.f; }

#pragma unroll
        for (int ks = 0; ks < 4; ++ks) {
            int k0 = ks * 16;
            const __nv_bfloat16* arh = EAh + (R + qr) * PAD + k0 + qc * 2;
            const __nv_bfloat16* arl = EAl + (R + qr) * PAD + k0 + qc * 2;
            uint32_t ah0 = *(const uint32_t*)(arh);
            uint32_t ah1 = *(const uint32_t*)(arh + 8 * PAD);
            uint32_t ah2 = *(const uint32_t*)(arh + 8);
            uint32_t ah3 = *(const uint32_t*)(arh + 8 * PAD + 8);
            uint32_t al0 = *(const uint32_t*)(arl);
            uint32_t al1 = *(const uint32_t*)(arl + 8 * PAD);
            uint32_t al2 = *(const uint32_t*)(arl + 8);
            uint32_t al3 = *(const uint32_t*)(arl + 8 * PAD + 8);
#pragma unroll
            for (int t = 0; t < 16; ++t) {
                const __nv_bfloat16* brh = WTh + (t * 8 + qr) * PAD + k0 + qc * 2;
                const __nv_bfloat16* brl = WTl + (t * 8 + qr) * PAD + k0 + qc * 2;
                uint32_t bh0 = *(const uint32_t*)(brh);
                uint32_t bh1 = *(const uint32_t*)(brh + 8);
                uint32_t bl0 = *(const uint32_t*)(brl);
                uint32_t bl1 = *(const uint32_t*)(brl + 8);
                mma16816(d[t][0], d[t][1], d[t][2], d[t][3],
                         ah0, ah1, ah2, ah3, bh0, bh1);
                mma16816(d[t][0], d[t][1], d[t][2], d[t][3],
                         al0, al1, al2, al3, bh0, bh1);
                mma16816(d[t][0], d[t][1], d[t][2], d[t][3],
                         ah0, ah1, ah2, ah3, bl0, bl1);
            }
        }
        __syncthreads();          // EA smem free for next tile's staging

        // ---- epilogue: two edge rows per lane (qr, qr+8) ----
#pragma unroll
        for (int half = 0; half < 2; ++half) {
            int r   = R + qr + half * 8;
            int src = sd[r], dst = dd[r];
            const float2* bx = (const float2*)(g_xw1 + (size_t)src * DO);

            float sum = 0.f;
#pragma unroll
            for (int t = 0; t < 16; ++t) {
                float2 b  = __ldg(bx + t * 4 + qc);
                float2 cv = c1f2[t * 4 + qc];
                float v0 = d[t][half * 2 + 0] + b.x + cv.x;
                float v1 = d[t][half * 2 + 1] + b.y + cv.y;
                v0 = v0 >= 0.f ? v0 : NEG_SLOPE * v0;
                v1 = v1 >= 0.f ? v1 : NEG_SLOPE * v1;
                d[t][half * 2 + 0] = v0;
                d[t][half * 2 + 1] = v1;
                sum += v0 + v1;
            }
            sum += __shfl_xor_sync(0xffffffffu, sum, 1);
            sum += __shfl_xor_sync(0xffffffffu, sum, 2);
            float mu = sum * (1.0f / DO);

            float vv = 0.f;
#pragma unroll
            for (int t = 0; t < 16; ++t) {
                float e0 = d[t][half * 2 + 0] - mu;
                float e1 = d[t][half * 2 + 1] - mu;
                vv += e0 * e0 + e1 * e1;
            }
            vv += __shfl_xor_sync(0xffffffffu, vv, 1);
            vv += __shfl_xor_sync(0xffffffffu, vv, 2);
            float inv = rsqrtf(vv * (1.0f / DO) + LN_EPS);

            if (base + r < E) {
                float* p = g_sums + (size_t)dst * DO;
#pragma unroll
                for (int t = 0; t < 16; ++t) {
                    float2 gv = g1f2[t * 4 + qc];
                    float2 bv = be1f2[t * 4 + qc];
                    float t0 = (d[t][half * 2 + 0] - mu) * inv * gv.x + bv.x;
                    float t1 = (d[t][half * 2 + 1] - mu) * inv * gv.y + bv.y;
                    asm volatile("red.global.add.v2.f32 [%0], {%1, %2};"
                                 :: "l"(p + t * 8 + qc * 2), "f"(t0), "f"(t1) : "memory");
                }
                if (qc == 0) atomicAdd(g_cnt + dst, 1.0f);
            }
        }
    }
}

// ---------------- kernel 4a: agg = (cnt>0) ? (sums/cnt)@W1b + b1b : 0 ------
__global__ void __launch_bounds__(256) node_a_kernel(
        const float* __restrict__ W1b,
        const float* __restrict__ b1b,
        int N) {
    extern __shared__ float sm[];
    float*  W1b_s  = sm;
    float*  b1b_s  = sm + DO * DO;
    float2* st_all = (float2*)(b1b_s + DO);

    for (int idx = threadIdx.x; idx < DO * DO; idx += blockDim.x)
        W1b_s[idx] = W1b[idx];
    if (threadIdx.x < DO) b1b_s[threadIdx.x] = b1b[threadIdx.x];
    __syncthreads();

    int lane = threadIdx.x & 31;
    int warp = threadIdx.x >> 5;
    float2*    st  = st_all + warp * (NPB * DO);
    const ull* stq = (const ull*)st;
    int gw = blockIdx.x * 8 + warp;
    int nw = gridDim.x * 8;

    float4 b4 = reinterpret_cast<float4*>(b1b_s)[lane];
    ull blo = pack2(b4.x, b4.y), bhi = pack2(b4.z, b4.w);

    for (int base = gw * NPB; base < N; base += nw * NPB) {
        int ne = min(NPB, N - base);
        float cnts[NPB];
        __syncwarp();
#pragma unroll
        for (int n = 0; n < NPB; ++n) {
            int node = (n < ne) ? base + n : base;
            float c = g_cnt[node];
            cnts[n] = c;
            float ic = c > 0.f ? (1.0f / c) : 0.f;
            float4 sv = reinterpret_cast<float4*>(g_sums)[(size_t)node * (DO / 4) + lane];
            st[n * DO + 4 * lane + 0] = make_float2(sv.x * ic, sv.x * ic);
            st[n * DO + 4 * lane + 1] = make_float2(sv.y * ic, sv.y * ic);
            st[n * DO + 4 * lane + 2] = make_float2(sv.z * ic, sv.z * ic);
            st[n * DO + 4 * lane + 3] = make_float2(sv.w * ic, sv.w * ic);
        }
        __syncwarp();

        ull alo[NPB], ahi[NPB];
#pragma unroll
        for (int n = 0; n < NPB; ++n) { alo[n] = blo; ahi[n] = bhi; }
#pragma unroll 2
        for (int k = 0; k < DO; ++k) {
            float4 w = reinterpret_cast<float4*>(W1b_s + k * DO)[lane];
            ull wlo = pack2(w.x, w.y), whi = pack2(w.z, w.w);
#pragma unroll
            for (int n = 0; n < NPB; ++n) {
                ull a = stq[n * DO + k];
                alo[n] = ffma2(wlo, a, alo[n]);
                ahi[n] = ffma2(whi, a, ahi[n]);
            }
        }
#pragma unroll
        for (int n = 0; n < NPB; ++n) {
            if (n < ne) {
                int node = base + n;
                float4 o;
                if (cnts[n] > 0.f) {
                    unpack2(alo[n], o.x, o.y); unpack2(ahi[n], o.z, o.w);
                } else {
                    o = make_float4(0.f, 0.f, 0.f, 0.f);
                }
                reinterpret_cast<float4*>(g_xw1)[(size_t)node * (DO / 4) + lane] = o;
            }
        }
    }
}

// ---------------- kernel 4b: final MLP (R3, unchanged) ---------------------
__global__ void __launch_bounds__(512) node_b_kernel(
        const float* __restrict__ W2a,
        const float* __restrict__ g2,
        const float* __restrict__ be2,
        const float* __restrict__ W2b,
        const float* __restrict__ b2b,
        float* __restrict__ out,
        int N) {
    extern __shared__ float sm[];
    float*  W2g_s  = sm;
    float*  W2b_s  = sm + DO * DO;
    float*  g2_s   = sm + 2 * DO * DO;
    float*  be2_s  = g2_s + DO;
    float*  b2b_s  = be2_s + DO;
    float2* st_all = (float2*)(b2b_s + DO);

    for (int idx = threadIdx.x; idx < DO * DO; idx += blockDim.x) {
        W2g_s[idx] = W2a[DN * DO + idx];
        W2b_s[idx] = W2b[idx];
    }
    if (threadIdx.x < DO) {
        g2_s [threadIdx.x] = g2 [threadIdx.x];
        be2_s[threadIdx.x] = be2[threadIdx.x];
        b2b_s[threadIdx.x] = b2b[threadIdx.x];
    }
    __syncthreads();

    int lane = threadIdx.x & 31;
    int warp = threadIdx.x >> 5;
    float2*    st  = st_all + warp * (NPB * DO);
    const ull* stq = (const ull*)st;
    int gw = blockIdx.x * (blockDim.x >> 5) + warp;
    int nw = gridDim.x * (blockDim.x >> 5);

    float4 gg = reinterpret_cast<float4*>(g2_s )[lane];
    float4 be = reinterpret_cast<float4*>(be2_s)[lane];
    float4 b4 = reinterpret_cast<float4*>(b2b_s)[lane];
    ull blo = pack2(b4.x, b4.y), bhi = pack2(b4.z, b4.w);

    for (int base = gw * NPB; base < N; base += nw * NPB) {
        int ne = min(NPB, N - base);
        __syncwarp();
        ull tlo[NPB], thi[NPB];
#pragma unroll
        for (int n = 0; n < NPB; ++n) {
            int node = (n < ne) ? base + n : base;
            float4 av = reinterpret_cast<float4*>(g_xw1)[(size_t)node * (DO / 4) + lane];
            st[n * DO + 4 * lane + 0] = make_float2(av.x, av.x);
            st[n * DO + 4 * lane + 1] = make_float2(av.y, av.y);
            st[n * DO + 4 * lane + 2] = make_float2(av.z, av.z);
            st[n * DO + 4 * lane + 3] = make_float2(av.w, av.w);
            float4 t0 = reinterpret_cast<float4*>(g_xw2)[(size_t)node * (DO / 4) + lane];
            tlo[n] = pack2(t0.x, t0.y);
            thi[n] = pack2(t0.z, t0.w);
        }
        __syncwarp();

#pragma unroll 2
        for (int k = 0; k < DO; ++k) {
            float4 w = reinterpret_cast<float4*>(W2g_s + k * DO)[lane];
            ull wlo = pack2(w.x, w.y), whi = pack2(w.z, w.w);
#pragma unroll
            for (int n = 0; n < NPB; ++n) {
                ull a = stq[n * DO + k];
                tlo[n] = ffma2(wlo, a, tlo[n]);
                thi[n] = ffma2(whi, a, thi[n]);
            }
        }

        __syncwarp();
#pragma unroll
        for (int n = 0; n < NPB; ++n) {
            float x0, x1, x2, x3;
            unpack2(tlo[n], x0, x1); unpack2(thi[n], x2, x3);
            x0 = x0 >= 0.f ? x0 : NEG_SLOPE * x0;
            x1 = x1 >= 0.f ? x1 : NEG_SLOPE * x1;
            x2 = x2 >= 0.f ? x2 : NEG_SLOPE * x2;
            x3 = x3 >= 0.f ? x3 : NEG_SLOPE * x3;

            float s = x0 + x1 + x2 + x3;
#pragma unroll
            for (int o = 16; o > 0; o >>= 1) s += __shfl_xor_sync(0xffffffffu, s, o);
            float mu = s * (1.0f / DO);
            float d0 = x0 - mu, d1 = x1 - mu, d2 = x2 - mu, d3 = x3 - mu;
            float vv = d0 * d0 + d1 * d1 + d2 * d2 + d3 * d3;
#pragma unroll
            for (int o = 16; o > 0; o >>= 1) vv += __shfl_xor_sync(0xffffffffu, vv, o);
            float inv = rsqrtf(vv * (1.0f / DO) + LN_EPS);

            float t0 = d0 * inv * gg.x + be.x;
            float t1 = d1 * inv * gg.y + be.y;
            float t2 = d2 * inv * gg.z + be.z;
            float t3 = d3 * inv * gg.w + be.w;
            st[n * DO + 4 * lane + 0] = make_float2(t0, t0);
            st[n * DO + 4 * lane + 1] = make_float2(t1, t1);
            st[n * DO + 4 * lane + 2] = make_float2(t2, t2);
            st[n * DO + 4 * lane + 3] = make_float2(t3, t3);
        }
        __syncwarp();

        ull olo[NPB], ohi[NPB];
#pragma unroll
        for (int n = 0; n < NPB; ++n) { olo[n] = blo; ohi[n] = bhi; }
#pragma unroll 2
        for (int k = 0; k < DO; ++k) {
            float4 w = reinterpret_cast<float4*>(W2b_s + k * DO)[lane];
            ull wlo = pack2(w.x, w.y), whi = pack2(w.z, w.w);
#pragma unroll
            for (int n = 0; n < NPB; ++n) {
                ull a = stq[n * DO + k];
                olo[n] = ffma2(wlo, a, olo[n]);
                ohi[n] = ffma2(whi, a, ohi[n]);
            }
        }
#pragma unroll
        for (int n = 0; n < NPB; ++n) {
            if (n < ne) {
                int node = base + n;
                float4 o;
                unpack2(olo[n], o.x, o.y); unpack2(ohi[n], o.z, o.w);
                reinterpret_cast<float4*>(out)[(size_t)node * (DO / 4) + lane] = o;
            }
        }
    }
}

// ---------------- launcher -------------------------------------------------
static bool g_attr_done = false;

extern "C" void kernel_launch(void* const* d_in, const int* in_sizes, int n_in,
                              void* d_out, int out_size) {
    const float* x   = (const float*)d_in[0];
    const int*   ei  = (const int*)  d_in[1];
    const float* ea  = (const float*)d_in[2];
    const float* u   = (const float*)d_in[3];
    const float* W1a = (const float*)d_in[5];
    const float* b1a = (const float*)d_in[6];
    const float* g1  = (const float*)d_in[7];
    const float* be1 = (const float*)d_in[8];
    const float* W1b = (const float*)d_in[9];
    const float* b1b = (const float*)d_in[10];
    const float* W2a = (const float*)d_in[11];
    const float* b2a = (const float*)d_in[12];
    const float* g2  = (const float*)d_in[13];
    const float* be2 = (const float*)d_in[14];
    const float* W2b = (const float*)d_in[15];
    const float* b2b = (const float*)d_in[16];
    float* out = (float*)d_out;

    int N = in_sizes[0] / DN;
    int E = in_sizes[2] / DE;

    const int PRE_SMEM  = (2 * DN * DO + DO) * 4 + 16 * NPB * DN * 8;
    const int EDGE_SMEM = 4 * 128 * PAD * 2 + 3 * 128 * 4 + 2 * 128 * 4;   // 76288 B
    const int NA_SMEM   = (DO * DO + DO) * 4 + 8 * NPB * DO * 8;
    const int NB_SMEM   = (2 * DO * DO + 3 * DO) * 4 + 16 * NPB * DO * 8;

    if (!g_attr_done) {
        cudaFuncSetAttribute(precompute_kernel, cudaFuncAttributeMaxDynamicSharedMemorySize, PRE_SMEM);
        cudaFuncSetAttribute(edge_kernel,       cudaFuncAttributeMaxDynamicSharedMemorySize, EDGE_SMEM);
        cudaFuncSetAttribute(node_a_kernel,     cudaFuncAttributeMaxDynamicSharedMemorySize, NA_SMEM);
        cudaFuncSetAttribute(node_b_kernel,     cudaFuncAttributeMaxDynamicSharedMemorySize, NB_SMEM);
        g_attr_done = true;
    }

    c1_kernel<<<1, 128>>>(W1a, b1a, u);
    zero_kernel<<<256, 256>>>(N * DO, N);
    precompute_kernel<<<148, 512, PRE_SMEM>>>(x, W1a, W2a, b2a, N);
    edge_kernel<<<296, 256, EDGE_SMEM>>>(ei, ea, W1a, g1, be1, E);
    node_a_kernel<<<296, 256, NA_SMEM>>>(W1b, b1b, N);
    node_b_kernel<<<148, 512, NB_SMEM>>>(W2a, g2, be2, W2b, b2b, out, N);
}

// round 9
// speedup vs baseline: 3.4481x; 1.4127x over previous
#include <cuda_runtime.h>
#include <cuda_bf16.h>
#include <cstdint>

#define NEG_SLOPE 0.01f
#define LN_EPS    1e-5f

#define DN 128
#define DE 64
#define DG 32
#define DO 128
#define MAXN 50000
#define PAD 72         // bf16/row for K=64 tiles (edge)
#define PAD2 136       // bf16/row for K=128 tiles (node)

typedef unsigned long long ull;

// ---------------- scratch (device globals) ---------------------------------
__device__ __align__(16) float g_xw1 [MAXN * DO];
__device__ __align__(16) float g_xw2 [MAXN * DO];
__device__ __align__(16) float g_sums[MAXN * DO];
__device__ __align__(16) float g_cnt [MAXN];
__device__ __align__(16) float g_c1  [DO];
__device__ __align__(16) float g_Wc  [DO * DO];   // W1b @ W2a_agg
__device__ __align__(16) float g_c2  [DO];        // b1b @ W2a_agg

// ---------------- warp-MMA helpers (baseline PTX, sm_80+) ------------------
__device__ __forceinline__ void mma16816(
        float& d0, float& d1, float& d2, float& d3,
        uint32_t a0, uint32_t a1, uint32_t a2, uint32_t a3,
        uint32_t b0, uint32_t b1) {
    asm volatile(
        "mma.sync.aligned.m16n8k16.row.col.f32.bf16.bf16.f32 "
        "{%0,%1,%2,%3}, {%4,%5,%6,%7}, {%8,%9}, {%0,%1,%2,%3};"
        : "+f"(d0), "+f"(d1), "+f"(d2), "+f"(d3)
        : "r"(a0), "r"(a1), "r"(a2), "r"(a3), "r"(b0), "r"(b1));
}
__device__ __forceinline__ uint32_t bfpair(float a, float b) {
    __nv_bfloat162 t = __floats2bfloat162_rn(a, b);
    return *reinterpret_cast<uint32_t*>(&t);
}
__device__ __forceinline__ void f4_to_hl(float4 v, ull& ph, ull& pl) {
    __nv_bfloat16 h0 = __float2bfloat16(v.x), h1 = __float2bfloat16(v.y);
    __nv_bfloat16 h2 = __float2bfloat16(v.z), h3 = __float2bfloat16(v.w);
    uint32_t hA = bfpair(v.x, v.y), hB = bfpair(v.z, v.w);
    uint32_t lA = bfpair(v.x - __bfloat162float(h0), v.y - __bfloat162float(h1));
    uint32_t lB = bfpair(v.z - __bfloat162float(h2), v.w - __bfloat162float(h3));
    ph = (ull)hA | ((ull)hB << 32);
    pl = (ull)lA | ((ull)lB << 32);
}

// generic K-step GEMM: D[16x128] per warp += A(hi/lo) @ B(hi/lo)^T, 3-term split
__device__ __forceinline__ void gemm_hl(
        const __nv_bfloat16* __restrict__ Ah, const __nv_bfloat16* __restrict__ Al,
        const __nv_bfloat16* __restrict__ Bh, const __nv_bfloat16* __restrict__ Bl,
        int R, int qr, int qc, float d[16][4], int ksteps, int pad) {
#pragma unroll
    for (int ks = 0; ks < 8; ++ks) {
        if (ks >= ksteps) break;
        int k0 = ks * 16;
        const __nv_bfloat16* arh = Ah + (R + qr) * pad + k0 + qc * 2;
        const __nv_bfloat16* arl = Al + (R + qr) * pad + k0 + qc * 2;
        uint32_t ah0 = *(const uint32_t*)(arh);
        uint32_t ah1 = *(const uint32_t*)(arh + 8 * pad);
        uint32_t ah2 = *(const uint32_t*)(arh + 8);
        uint32_t ah3 = *(const uint32_t*)(arh + 8 * pad + 8);
        uint32_t al0 = *(const uint32_t*)(arl);
        uint32_t al1 = *(const uint32_t*)(arl + 8 * pad);
        uint32_t al2 = *(const uint32_t*)(arl + 8);
        uint32_t al3 = *(const uint32_t*)(arl + 8 * pad + 8);
#pragma unroll
        for (int t = 0; t < 16; ++t) {
            const __nv_bfloat16* brh = Bh + (t * 8 + qr) * pad + k0 + qc * 2;
            const __nv_bfloat16* brl = Bl + (t * 8 + qr) * pad + k0 + qc * 2;
            uint32_t bh0 = *(const uint32_t*)(brh);
            uint32_t bh1 = *(const uint32_t*)(brh + 8);
            uint32_t bl0 = *(const uint32_t*)(brl);
            uint32_t bl1 = *(const uint32_t*)(brl + 8);
            mma16816(d[t][0], d[t][1], d[t][2], d[t][3], ah0, ah1, ah2, ah3, bh0, bh1);
            mma16816(d[t][0], d[t][1], d[t][2], d[t][3], al0, al1, al2, al3, bh0, bh1);
            mma16816(d[t][0], d[t][1], d[t][2], d[t][3], ah0, ah1, ah2, ah3, bl0, bl1);
        }
    }
}

// ---------------- kernel 0: c1 = u @ Wu + b1a ------------------------------
__global__ void c1_kernel(const float* __restrict__ W1a,
                          const float* __restrict__ b1a,
                          const float* __restrict__ u) {
    int j = threadIdx.x;
    float acc = b1a[j];
#pragma unroll
    for (int k = 0; k < DG; ++k)
        acc += u[k] * W1a[(DN + DE + k) * DO + j];
    g_c1[j] = acc;
}

// ---------------- kernel W: Wc = W1b @ W2a_agg ; c2 = b1b @ W2a_agg --------
__global__ void wc_kernel(const float* __restrict__ W1b,
                          const float* __restrict__ b1b,
                          const float* __restrict__ W2a) {
    __shared__ float row[DO];
    int j = threadIdx.x;
    int i = blockIdx.x;
    row[j] = (i < DO) ? W1b[i * DO + j] : b1b[j];
    __syncthreads();
    float acc = 0.f;
#pragma unroll 8
    for (int k = 0; k < DO; ++k)
        acc += row[k] * W2a[(DN + k) * DO + j];
    if (i < DO) g_Wc[i * DO + j] = acc;
    else        g_c2[j] = acc;
}

// ---------------- kernel 1: zero scatter buffers ---------------------------
__global__ void zero_kernel(int n_sum, int n_cnt) {
    int i      = blockIdx.x * blockDim.x + threadIdx.x;
    int stride = gridDim.x * blockDim.x;
    for (int idx = i; idx < n_sum; idx += stride) g_sums[idx] = 0.0f;
    for (int idx = i; idx < n_cnt; idx += stride) g_cnt[idx]  = 0.0f;
}

// ---------------- kernel 2: precompute via MMA -----------------------------
// xw1 = x @ Wx ; xw2 = x @ W2a_x + b2a      (tiles of 128 nodes, warp-local)
__global__ void __launch_bounds__(256, 1) precompute_mma(
        const float* __restrict__ x,
        const float* __restrict__ W1a,
        const float* __restrict__ W2a,
        const float* __restrict__ b2a,
        int N) {
    extern __shared__ __align__(16) char smraw[];
    __nv_bfloat16* Xh  = (__nv_bfloat16*)smraw;
    __nv_bfloat16* Xl  = Xh  + 128 * PAD2;
    __nv_bfloat16* Wxh = Xl  + 128 * PAD2;
    __nv_bfloat16* Wxl = Wxh + 128 * PAD2;
    __nv_bfloat16* W2h = Wxl + 128 * PAD2;
    __nv_bfloat16* W2l = W2h + 128 * PAD2;
    float* b2as = (float*)(W2l + 128 * PAD2);

    int tid = threadIdx.x;
    for (int idx = tid; idx < DO * DN; idx += 256) {
        int k = idx >> 7, o = idx & 127;
        float v = W1a[idx];
        __nv_bfloat16 h = __float2bfloat16(v);
        Wxh[o * PAD2 + k] = h;
        Wxl[o * PAD2 + k] = __float2bfloat16(v - __bfloat162float(h));
        float w = W2a[idx];
        __nv_bfloat16 h2 = __float2bfloat16(w);
        W2h[o * PAD2 + k] = h2;
        W2l[o * PAD2 + k] = __float2bfloat16(w - __bfloat162float(h2));
    }
    if (tid < DO) b2as[tid] = b2a[tid];
    __syncthreads();

    int warp = tid >> 5, lane = tid & 31;
    int R = warp * 16, qr = lane >> 2, qc = lane & 3;
    const float2* b2f2 = (const float2*)b2as;

    int srow = tid >> 1, skb = (tid & 1) * 64;
    int ntiles = (N + 127) >> 7;
    for (int tile = blockIdx.x; tile < ntiles; tile += gridDim.x) {
        int base = tile << 7;
        // stage own warp's 16 rows
        {
            int node = base + srow; if (node >= N) node = N - 1;
            const float4* s = (const float4*)(x + (size_t)node * DN + skb);
            ull* ph = (ull*)(Xh + srow * PAD2 + skb);
            ull* pl = (ull*)(Xl + srow * PAD2 + skb);
#pragma unroll
            for (int j = 0; j < 16; ++j) f4_to_hl(s[j], ph[j], pl[j]);
        }
        __syncwarp();

        float d[16][4];
        // ---- pass 1: xw1 = x @ Wx ----
#pragma unroll
        for (int t = 0; t < 16; ++t) d[t][0] = d[t][1] = d[t][2] = d[t][3] = 0.f;
        gemm_hl(Xh, Xl, Wxh, Wxl, R, qr, qc, d, 8, PAD2);
#pragma unroll
        for (int half = 0; half < 2; ++half) {
            int node = base + R + qr + half * 8;
            if (node < N) {
                float2* o = (float2*)(g_xw1 + (size_t)node * DO);
#pragma unroll
                for (int t = 0; t < 16; ++t)
                    o[t * 4 + qc] = make_float2(d[t][half * 2], d[t][half * 2 + 1]);
            }
        }
        // ---- pass 2: xw2 = x @ W2a_x + b2a ----
#pragma unroll
        for (int t = 0; t < 16; ++t) d[t][0] = d[t][1] = d[t][2] = d[t][3] = 0.f;
        gemm_hl(Xh, Xl, W2h, W2l, R, qr, qc, d, 8, PAD2);
#pragma unroll
        for (int half = 0; half < 2; ++half) {
            int node = base + R + qr + half * 8;
            if (node < N) {
                float2* o = (float2*)(g_xw2 + (size_t)node * DO);
#pragma unroll
                for (int t = 0; t < 16; ++t) {
                    float2 b = b2f2[t * 4 + qc];
                    o[t * 4 + qc] = make_float2(d[t][half * 2] + b.x,
                                                d[t][half * 2 + 1] + b.y);
                }
            }
        }
        __syncwarp();
    }
}

// ---------------- kernel 3: edge phase (R7, unchanged) ---------------------
__global__ void __launch_bounds__(256, 2) edge_kernel(
        const int*   __restrict__ ei,
        const float* __restrict__ ea,
        const float* __restrict__ W1a,
        const float* __restrict__ g1,
        const float* __restrict__ be1,
        int E) {
    extern __shared__ __align__(16) char smraw[];
    __nv_bfloat16* EAh = (__nv_bfloat16*)smraw;
    __nv_bfloat16* EAl = EAh + 128 * PAD;
    __nv_bfloat16* WTh = EAl + 128 * PAD;
    __nv_bfloat16* WTl = WTh + 128 * PAD;
    float* c1s  = (float*)(WTl + 128 * PAD);
    float* g1s  = c1s + 128;
    float* be1s = g1s + 128;
    int*   sd   = (int*)(be1s + 128);
    int*   dd   = sd + 128;

    int tid = threadIdx.x;
    for (int idx = tid; idx < DE * DO; idx += 256) {
        int k = idx >> 7, o = idx & 127;
        float v = W1a[(DN + k) * DO + o];
        __nv_bfloat16 h = __float2bfloat16(v);
        __nv_bfloat16 l = __float2bfloat16(v - __bfloat162float(h));
        WTh[o * PAD + k] = h;
        WTl[o * PAD + k] = l;
    }
    if (tid < 128) {
        c1s [tid] = g_c1[tid];
        g1s [tid] = g1  [tid];
        be1s[tid] = be1 [tid];
    }

    int warp = tid >> 5, lane = tid & 31;
    int R  = warp * 16;
    int qr = lane >> 2, qc = lane & 3;

    const float2* c1f2  = (const float2*)c1s;
    const float2* g1f2  = (const float2*)g1s;
    const float2* be1f2 = (const float2*)be1s;

    int ntiles = (E + 127) >> 7;
    for (int tile = blockIdx.x; tile < ntiles; tile += gridDim.x) {
        int base = tile << 7;
        __syncthreads();
        {
            int e  = tid >> 1;
            int kb = (tid & 1) * 32;
            int eg = base + e; if (eg >= E) eg = E - 1;
            const float4* s = (const float4*)(ea + (size_t)eg * DE + kb);
            ull* ph = (ull*)(EAh + e * PAD + kb);
            ull* pl = (ull*)(EAl + e * PAD + kb);
#pragma unroll
            for (int j = 0; j < 8; ++j) f4_to_hl(s[j], ph[j], pl[j]);
            if (tid < 128) {
                int eg2 = base + tid; if (eg2 >= E) eg2 = E - 1;
                sd[tid] = ei[eg2];
                dd[tid] = ei[E + eg2];
            }
        }
        __syncthreads();

        float d[16][4];
#pragma unroll
        for (int t = 0; t < 16; ++t) { d[t][0] = d[t][1] = d[t][2] = d[t][3] = 0.f; }
        gemm_hl(EAh, EAl, WTh, WTl, R, qr, qc, d, 4, PAD);
        __syncthreads();

#pragma unroll
        for (int half = 0; half < 2; ++half) {
            int r   = R + qr + half * 8;
            int src = sd[r], dst = dd[r];
            const float2* bx = (const float2*)(g_xw1 + (size_t)src * DO);

            float sum = 0.f;
#pragma unroll
            for (int t = 0; t < 16; ++t) {
                float2 b  = __ldg(bx + t * 4 + qc);
                float2 cv = c1f2[t * 4 + qc];
                float v0 = d[t][half * 2 + 0] + b.x + cv.x;
                float v1 = d[t][half * 2 + 1] + b.y + cv.y;
                v0 = v0 >= 0.f ? v0 : NEG_SLOPE * v0;
                v1 = v1 >= 0.f ? v1 : NEG_SLOPE * v1;
                d[t][half * 2 + 0] = v0;
                d[t][half * 2 + 1] = v1;
                sum += v0 + v1;
            }
            sum += __shfl_xor_sync(0xffffffffu, sum, 1);
            sum += __shfl_xor_sync(0xffffffffu, sum, 2);
            float mu = sum * (1.0f / DO);

            float vv = 0.f;
#pragma unroll
            for (int t = 0; t < 16; ++t) {
                float e0 = d[t][half * 2 + 0] - mu;
                float e1 = d[t][half * 2 + 1] - mu;
                vv += e0 * e0 + e1 * e1;
            }
            vv += __shfl_xor_sync(0xffffffffu, vv, 1);
            vv += __shfl_xor_sync(0xffffffffu, vv, 2);
            float inv = rsqrtf(vv * (1.0f / DO) + LN_EPS);

            if (base + r < E) {
                float* p = g_sums + (size_t)dst * DO;
#pragma unroll
                for (int t = 0; t < 16; ++t) {
                    float2 gv = g1f2[t * 4 + qc];
                    float2 bv = be1f2[t * 4 + qc];
                    float t0 = (d[t][half * 2 + 0] - mu) * inv * gv.x + bv.x;
                    float t1 = (d[t][half * 2 + 1] - mu) * inv * gv.y + bv.y;
                    asm volatile("red.global.add.v2.f32 [%0], {%1, %2};"
                                 :: "l"(p + t * 8 + qc * 2), "f"(t0), "f"(t1) : "memory");
                }
                if (qc == 0) atomicAdd(g_cnt + dst, 1.0f);
            }
        }
    }
}

// ---------------- kernel 4: fused node MLP via MMA -------------------------
// mean = sums/cnt ; t = xw2 + (cnt>0 ? mean@Wc + c2 : 0) ; LeakyReLU ;
// LN(g2,be2) ; out = t_ln @ W2b + b2b
__global__ void __launch_bounds__(256, 1) node_fused(
        const float* __restrict__ W2b,
        const float* __restrict__ g2,
        const float* __restrict__ be2,
        const float* __restrict__ b2b,
        float* __restrict__ out,
        int N) {
    extern __shared__ __align__(16) char smraw[];
    __nv_bfloat16* Th  = (__nv_bfloat16*)smraw;
    __nv_bfloat16* Tl  = Th  + 128 * PAD2;
    __nv_bfloat16* Wch = Tl  + 128 * PAD2;
    __nv_bfloat16* Wcl = Wch + 128 * PAD2;
    __nv_bfloat16* Wbh = Wcl + 128 * PAD2;
    __nv_bfloat16* Wbl = Wbh + 128 * PAD2;
    float* cs   = (float*)(Wbl + 128 * PAD2);  // 128
    float* c2s  = cs  + 128;
    float* g2s  = c2s + 128;
    float* be2s = g2s + 128;
    float* b2bs = be2s + 128;

    int tid = threadIdx.x;
    for (int idx = tid; idx < DO * DO; idx += 256) {
        int k = idx >> 7, o = idx & 127;
        float v = g_Wc[idx];
        __nv_bfloat16 h = __float2bfloat16(v);
        Wch[o * PAD2 + k] = h;
        Wcl[o * PAD2 + k] = __float2bfloat16(v - __bfloat162float(h));
        float w = W2b[idx];
        __nv_bfloat16 h2 = __float2bfloat16(w);
        Wbh[o * PAD2 + k] = h2;
        Wbl[o * PAD2 + k] = __float2bfloat16(w - __bfloat162float(h2));
    }
    if (tid < DO) {
        c2s [tid] = g_c2[tid];
        g2s [tid] = g2 [tid];
        be2s[tid] = be2[tid];
        b2bs[tid] = b2b[tid];
    }
    __syncthreads();

    int warp = tid >> 5, lane = tid & 31;
    int R = warp * 16, qr = lane >> 2, qc = lane & 3;
    const float2* c2f2  = (const float2*)c2s;
    const float2* g2f2  = (const float2*)g2s;
    const float2* be2f2 = (const float2*)be2s;
    const float2* b2bf2 = (const float2*)b2bs;

    int srow = tid >> 1, skb = (tid & 1) * 64;
    int ntiles = (N + 127) >> 7;
    for (int tile = blockIdx.x; tile < ntiles; tile += gridDim.x) {
        int base = tile << 7;
        // stage own warp's 16 rows of mean
        {
            int node = base + srow; if (node >= N) node = N - 1;
            float cn = g_cnt[node];
            float ic = cn > 0.f ? (1.0f / cn) : 0.f;
            if ((tid & 1) == 0) cs[srow] = cn;
            const float4* s = (const float4*)(g_sums + (size_t)node * DO + skb);
            ull* ph = (ull*)(Th + srow * PAD2 + skb);
            ull* pl = (ull*)(Tl + srow * PAD2 + skb);
#pragma unroll
            for (int j = 0; j < 16; ++j) {
                float4 v = s[j];
                v.x *= ic; v.y *= ic; v.z *= ic; v.w *= ic;
                f4_to_hl(v, ph[j], pl[j]);
            }
        }
        __syncwarp();

        // GEMM1: d = mean @ Wc
        float d[16][4];
#pragma unroll
        for (int t = 0; t < 16; ++t) d[t][0] = d[t][1] = d[t][2] = d[t][3] = 0.f;
        gemm_hl(Th, Tl, Wch, Wcl, R, qr, qc, d, 8, PAD2);
        __syncwarp();   // all lanes done reading mean tile before overwrite

        // epilogue1: t = d + xw2 + (cnt>0 ? c2 : 0); Leaky; LN; restage bf16
#pragma unroll
        for (int half = 0; half < 2; ++half) {
            int r = R + qr + half * 8;
            int node = base + r; if (node >= N) node = N - 1;
            float cnr = cs[r];
            const float2* xw = (const float2*)(g_xw2 + (size_t)node * DO);

            float sum = 0.f;
#pragma unroll
            for (int t = 0; t < 16; ++t) {
                float2 b  = __ldg(xw + t * 4 + qc);
                float2 cv = c2f2[t * 4 + qc];
                float add0 = cnr > 0.f ? cv.x : 0.f;
                float add1 = cnr > 0.f ? cv.y : 0.f;
                float v0 = d[t][half * 2 + 0] + b.x + add0;
                float v1 = d[t][half * 2 + 1] + b.y + add1;
                v0 = v0 >= 0.f ? v0 : NEG_SLOPE * v0;
                v1 = v1 >= 0.f ? v1 : NEG_SLOPE * v1;
                d[t][half * 2 + 0] = v0;
                d[t][half * 2 + 1] = v1;
                sum += v0 + v1;
            }
            sum += __shfl_xor_sync(0xffffffffu, sum, 1);
            sum += __shfl_xor_sync(0xffffffffu, sum, 2);
            float mu = sum * (1.0f / DO);

            float vv = 0.f;
#pragma unroll
            for (int t = 0; t < 16; ++t) {
                float e0 = d[t][half * 2 + 0] - mu;
                float e1 = d[t][half * 2 + 1] - mu;
                vv += e0 * e0 + e1 * e1;
            }
            vv += __shfl_xor_sync(0xffffffffu, vv, 1);
            vv += __shfl_xor_sync(0xffffffffu, vv, 2);
            float inv = rsqrtf(vv * (1.0f / DO) + LN_EPS);

#pragma unroll
            for (int t = 0; t < 16; ++t) {
                float2 gv = g2f2[t * 4 + qc];
                float2 bv = be2f2[t * 4 + qc];
                float t0 = (d[t][half * 2 + 0] - mu) * inv * gv.x + bv.x;
                float t1 = (d[t][half * 2 + 1] - mu) * inv * gv.y + bv.y;
                __nv_bfloat16 h0 = __float2bfloat16(t0);
                __nv_bfloat16 h1 = __float2bfloat16(t1);
                int off = r * PAD2 + t * 8 + 2 * qc;
                *(uint32_t*)(Th + off) = bfpair(t0, t1);
                *(uint32_t*)(Tl + off) = bfpair(t0 - __bfloat162float(h0),
                                                t1 - __bfloat162float(h1));
            }
        }
        __syncwarp();

        // GEMM2: out = t_ln @ W2b + b2b
#pragma unroll
        for (int t = 0; t < 16; ++t) d[t][0] = d[t][1] = d[t][2] = d[t][3] = 0.f;
        gemm_hl(Th, Tl, Wbh, Wbl, R, qr, qc, d, 8, PAD2);

#pragma unroll
        for (int half = 0; half < 2; ++half) {
            int node = base + R + qr + half * 8;
            if (node < N) {
                float2* o = (float2*)(out + (size_t)node * DO);
#pragma unroll
                for (int t = 0; t < 16; ++t) {
                    float2 b = b2bf2[t * 4 + qc];
                    o[t * 4 + qc] = make_float2(d[t][half * 2] + b.x,
                                                d[t][half * 2 + 1] + b.y);
                }
            }
        }
        __syncwarp();
    }
}

// ---------------- launcher -------------------------------------------------
static bool g_attr_done = false;

extern "C" void kernel_launch(void* const* d_in, const int* in_sizes, int n_in,
                              void* d_out, int out_size) {
    const float* x   = (const float*)d_in[0];
    const int*   ei  = (const int*)  d_in[1];
    const float* ea  = (const float*)d_in[2];
    const float* u   = (const float*)d_in[3];
    const float* W1a = (const float*)d_in[5];
    const float* b1a = (const float*)d_in[6];
    const float* g1  = (const float*)d_in[7];
    const float* be1 = (const float*)d_in[8];
    const float* W1b = (const float*)d_in[9];
    const float* b1b = (const float*)d_in[10];
    const float* W2a = (const float*)d_in[11];
    const float* b2a = (const float*)d_in[12];
    const float* g2  = (const float*)d_in[13];
    const float* be2 = (const float*)d_in[14];
    const float* W2b = (const float*)d_in[15];
    const float* b2b = (const float*)d_in[16];
    float* out = (float*)d_out;

    int N = in_sizes[0] / DN;
    int E = in_sizes[2] / DE;

    const int PRE2_SMEM = 6 * 128 * PAD2 * 2 + 128 * 4;                    // 209408
    const int EDGE_SMEM = 4 * 128 * PAD * 2 + 3 * 128 * 4 + 2 * 128 * 4;   // 76288
    const int NF_SMEM   = 6 * 128 * PAD2 * 2 + 5 * 128 * 4;                // 211456

    if (!g_attr_done) {
        cudaFuncSetAttribute(precompute_mma, cudaFuncAttributeMaxDynamicSharedMemorySize, PRE2_SMEM);
        cudaFuncSetAttribute(edge_kernel,    cudaFuncAttributeMaxDynamicSharedMemorySize, EDGE_SMEM);
        cudaFuncSetAttribute(node_fused,     cudaFuncAttributeMaxDynamicSharedMemorySize, NF_SMEM);
        g_attr_done = true;
    }

    c1_kernel<<<1, 128>>>(W1a, b1a, u);
    wc_kernel<<<129, 128>>>(W1b, b1b, W2a);
    zero_kernel<<<256, 256>>>(N * DO, N);
    precompute_mma<<<148, 256, PRE2_SMEM>>>(x, W1a, W2a, b2a, N);
    edge_kernel<<<296, 256, EDGE_SMEM>>>(ei, ea, W1a, g1, be1, E);
    node_fused<<<148, 256, NF_SMEM>>>(W2b, g2, be2, b2b, out, N);
}

// round 11
// speedup vs baseline: 3.6639x; 1.0626x over previous
#include <cuda_runtime.h>
#include <cuda_bf16.h>
#include <cstdint>

#define NEG_SLOPE 0.01f
#define LN_EPS    1e-5f

#define DN 128
#define DE 64
#define DG 32
#define DO 128
#define MAXN 50000
#define PAD 72         // bf16/row for K=64 tiles (edge)
#define PAD2 136       // bf16/row for K=128 tiles (node)

typedef unsigned long long ull;

// ---------------- scratch (device globals) ---------------------------------
__device__ __align__(16) float g_xw1 [MAXN * DO];   // x@Wx + c1 (edge bias)
__device__ __align__(16) float g_xw2 [MAXN * DO];   // x@W2a_x + b2a
__device__ __align__(16) float g_sums[MAXN * DO];
__device__ __align__(16) float g_cnt [MAXN];
__device__ __align__(16) float g_c1  [DO];
__device__ __align__(16) float g_Wc  [DO * DO];     // W1b @ W2a_agg
__device__ __align__(16) float g_c2  [DO];          // b1b @ W2a_agg

// ---------------- warp-MMA helpers (baseline PTX, sm_80+) ------------------
__device__ __forceinline__ void mma16816(
        float& d0, float& d1, float& d2, float& d3,
        uint32_t a0, uint32_t a1, uint32_t a2, uint32_t a3,
        uint32_t b0, uint32_t b1) {
    asm volatile(
        "mma.sync.aligned.m16n8k16.row.col.f32.bf16.bf16.f32 "
        "{%0,%1,%2,%3}, {%4,%5,%6,%7}, {%8,%9}, {%0,%1,%2,%3};"
        : "+f"(d0), "+f"(d1), "+f"(d2), "+f"(d3)
        : "r"(a0), "r"(a1), "r"(a2), "r"(a3), "r"(b0), "r"(b1));
}
__device__ __forceinline__ void ldsm_x4(
        uint32_t& r0, uint32_t& r1, uint32_t& r2, uint32_t& r3, uint32_t addr) {
    asm volatile("ldmatrix.sync.aligned.m8n8.x4.shared.b16 {%0,%1,%2,%3}, [%4];"
        : "=r"(r0), "=r"(r1), "=r"(r2), "=r"(r3) : "r"(addr));
}
__device__ __forceinline__ uint32_t bfpair(float a, float b) {
    __nv_bfloat162 t = __floats2bfloat162_rn(a, b);
    return *reinterpret_cast<uint32_t*>(&t);
}
__device__ __forceinline__ void f4_to_hl(float4 v, ull& ph, ull& pl) {
    __nv_bfloat16 h0 = __float2bfloat16(v.x), h1 = __float2bfloat16(v.y);
    __nv_bfloat16 h2 = __float2bfloat16(v.z), h3 = __float2bfloat16(v.w);
    uint32_t hA = bfpair(v.x, v.y), hB = bfpair(v.z, v.w);
    uint32_t lA = bfpair(v.x - __bfloat162float(h0), v.y - __bfloat162float(h1));
    uint32_t lB = bfpair(v.z - __bfloat162float(h2), v.w - __bfloat162float(h3));
    ph = (ull)hA | ((ull)hB << 32);
    pl = (ull)lA | ((ull)lB << 32);
}

// D[16x128] per warp += A(hi/lo) @ B(hi/lo)^T via ldmatrix fragments.
// A lane map (x4):   lanes 0-15 rows R+(l&15) @k0, lanes 16-31 same rows @k0+8
// B lane map (x4):   m=l>>3: rows tpair*16 + (m>>1)*8 + (l&7), k = k0 + (m&1)*8
__device__ __forceinline__ void gemm_hl(
        uint32_t sAh, uint32_t sAl, uint32_t sBh, uint32_t sBl,
        int R, int lane, float d[16][4], int ksteps, int pad) {
    uint32_t aoff = ((R + (lane & 15)) * pad + ((lane >> 4) << 3)) * 2;
    int m = lane >> 3;
    uint32_t boff = (((m >> 1) * 8 + (lane & 7)) * pad + ((m & 1) << 3)) * 2;
#pragma unroll
    for (int ks = 0; ks < 8; ++ks) {
        if (ks >= ksteps) break;
        uint32_t ka = (uint32_t)(ks * 16 * 2);
        uint32_t ah0, ah1, ah2, ah3, al0, al1, al2, al3;
        ldsm_x4(ah0, ah1, ah2, ah3, sAh + aoff + ka);
        ldsm_x4(al0, al1, al2, al3, sAl + aoff + ka);
#pragma unroll
        for (int tt = 0; tt < 8; ++tt) {
            uint32_t bo = boff + (uint32_t)(tt * 16 * pad * 2) + ka;
            uint32_t bh0, bh1, bh2, bh3, bl0, bl1, bl2, bl3;
            ldsm_x4(bh0, bh1, bh2, bh3, sBh + bo);
            ldsm_x4(bl0, bl1, bl2, bl3, sBl + bo);
            int t0 = 2 * tt, t1 = 2 * tt + 1;
            mma16816(d[t0][0], d[t0][1], d[t0][2], d[t0][3], ah0, ah1, ah2, ah3, bh0, bh1);
            mma16816(d[t0][0], d[t0][1], d[t0][2], d[t0][3], al0, al1, al2, al3, bh0, bh1);
            mma16816(d[t0][0], d[t0][1], d[t0][2], d[t0][3], ah0, ah1, ah2, ah3, bl0, bl1);
            mma16816(d[t1][0], d[t1][1], d[t1][2], d[t1][3], ah0, ah1, ah2, ah3, bh2, bh3);
            mma16816(d[t1][0], d[t1][1], d[t1][2], d[t1][3], al0, al1, al2, al3, bh2, bh3);
            mma16816(d[t1][0], d[t1][1], d[t1][2], d[t1][3], ah0, ah1, ah2, ah3, bl2, bl3);
        }
    }
}

// ---------------- kernel 0: c1 = u @ Wu + b1a ------------------------------
__global__ void c1_kernel(const float* __restrict__ W1a,
                          const float* __restrict__ b1a,
                          const float* __restrict__ u) {
    int j = threadIdx.x;
    float acc = b1a[j];
#pragma unroll
    for (int k = 0; k < DG; ++k)
        acc += u[k] * W1a[(DN + DE + k) * DO + j];
    g_c1[j] = acc;
}

// ---------------- kernel W: Wc = W1b @ W2a_agg ; c2 = b1b @ W2a_agg --------
__global__ void wc_kernel(const float* __restrict__ W1b,
                          const float* __restrict__ b1b,
                          const float* __restrict__ W2a) {
    __shared__ float row[DO];
    int j = threadIdx.x;
    int i = blockIdx.x;
    row[j] = (i < DO) ? W1b[i * DO + j] : b1b[j];
    __syncthreads();
    float acc = 0.f;
#pragma unroll 8
    for (int k = 0; k < DO; ++k)
        acc += row[k] * W2a[(DN + k) * DO + j];
    if (i < DO) g_Wc[i * DO + j] = acc;
    else        g_c2[j] = acc;
}

// ---------------- kernel 1: zero scatter buffers ---------------------------
__global__ void zero_kernel(int n_sum, int n_cnt) {
    int i      = blockIdx.x * blockDim.x + threadIdx.x;
    int stride = gridDim.x * blockDim.x;
    for (int idx = i; idx < n_sum; idx += stride) g_sums[idx] = 0.0f;
    for (int idx = i; idx < n_cnt; idx += stride) g_cnt[idx]  = 0.0f;
}

// ---------------- kernel 2: precompute via MMA -----------------------------
// xw1 = x @ Wx + c1 (broadcast) ; xw2 = x @ W2a_x + b2a
__global__ void __launch_bounds__(256, 1) precompute_mma(
        const float* __restrict__ x,
        const float* __restrict__ W1a,
        const float* __restrict__ W2a,
        const float* __restrict__ b2a,
        int N) {
    extern __shared__ __align__(16) char smraw[];
    __nv_bfloat16* Xh  = (__nv_bfloat16*)smraw;
    __nv_bfloat16* Xl  = Xh  + 128 * PAD2;
    __nv_bfloat16* Wxh = Xl  + 128 * PAD2;
    __nv_bfloat16* Wxl = Wxh + 128 * PAD2;
    __nv_bfloat16* W2h = Wxl + 128 * PAD2;
    __nv_bfloat16* W2l = W2h + 128 * PAD2;
    float* b2as = (float*)(W2l + 128 * PAD2);
    float* c1s  = b2as + DO;

    int tid = threadIdx.x;
    for (int idx = tid; idx < DO * DN; idx += 256) {
        int k = idx >> 7, o = idx & 127;
        float v = W1a[idx];
        __nv_bfloat16 h = __float2bfloat16(v);
        Wxh[o * PAD2 + k] = h;
        Wxl[o * PAD2 + k] = __float2bfloat16(v - __bfloat162float(h));
        float w = W2a[idx];
        __nv_bfloat16 h2 = __float2bfloat16(w);
        W2h[o * PAD2 + k] = h2;
        W2l[o * PAD2 + k] = __float2bfloat16(w - __bfloat162float(h2));
    }
    if (tid < DO) {
        b2as[tid] = b2a[tid];
        c1s [tid] = g_c1[tid];
    }
    __syncthreads();

    uint32_t sXh  = (uint32_t)__cvta_generic_to_shared(Xh);
    uint32_t sXl  = (uint32_t)__cvta_generic_to_shared(Xl);
    uint32_t sWxh = (uint32_t)__cvta_generic_to_shared(Wxh);
    uint32_t sWxl = (uint32_t)__cvta_generic_to_shared(Wxl);
    uint32_t sW2h = (uint32_t)__cvta_generic_to_shared(W2h);
    uint32_t sW2l = (uint32_t)__cvta_generic_to_shared(W2l);

    int warp = tid >> 5, lane = tid & 31;
    int R = warp * 16, qr = lane >> 2, qc = lane & 3;
    const float2* b2f2 = (const float2*)b2as;
    const float2* c1f2 = (const float2*)c1s;

    int srow = tid >> 1, skb = (tid & 1) * 64;
    int ntiles = (N + 127) >> 7;
    for (int tile = blockIdx.x; tile < ntiles; tile += gridDim.x) {
        int base = tile << 7;
        {
            int node = base + srow; if (node >= N) node = N - 1;
            const float4* s = (const float4*)(x + (size_t)node * DN + skb);
            ull* ph = (ull*)(Xh + srow * PAD2 + skb);
            ull* pl = (ull*)(Xl + srow * PAD2 + skb);
#pragma unroll
            for (int j = 0; j < 16; ++j) f4_to_hl(s[j], ph[j], pl[j]);
        }
        __syncwarp();

        float d[16][4];
#pragma unroll
        for (int t = 0; t < 16; ++t) d[t][0] = d[t][1] = d[t][2] = d[t][3] = 0.f;
        gemm_hl(sXh, sXl, sWxh, sWxl, R, lane, d, 8, PAD2);
#pragma unroll
        for (int half = 0; half < 2; ++half) {
            int node = base + R + qr + half * 8;
            if (node < N) {
                float2* o = (float2*)(g_xw1 + (size_t)node * DO);
#pragma unroll
                for (int t = 0; t < 16; ++t) {
                    float2 cv = c1f2[t * 4 + qc];
                    o[t * 4 + qc] = make_float2(d[t][half * 2] + cv.x,
                                                d[t][half * 2 + 1] + cv.y);
                }
            }
        }
#pragma unroll
        for (int t = 0; t < 16; ++t) d[t][0] = d[t][1] = d[t][2] = d[t][3] = 0.f;
        gemm_hl(sXh, sXl, sW2h, sW2l, R, lane, d, 8, PAD2);
#pragma unroll
        for (int half = 0; half < 2; ++half) {
            int node = base + R + qr + half * 8;
            if (node < N) {
                float2* o = (float2*)(g_xw2 + (size_t)node * DO);
#pragma unroll
                for (int t = 0; t < 16; ++t) {
                    float2 b = b2f2[t * 4 + qc];
                    o[t * 4 + qc] = make_float2(d[t][half * 2] + b.x,
                                                d[t][half * 2 + 1] + b.y);
                }
            }
        }
        __syncwarp();
    }
}

// ---------------- kernel 3: edge phase (mma + ldmatrix) --------------------
__global__ void __launch_bounds__(256, 2) edge_kernel(
        const int*   __restrict__ ei,
        const float* __restrict__ ea,
        const float* __restrict__ W1a,
        const float* __restrict__ g1,
        const float* __restrict__ be1,
        int E) {
    extern __shared__ __align__(16) char smraw[];
    __nv_bfloat16* EAh = (__nv_bfloat16*)smraw;
    __nv_bfloat16* EAl = EAh + 128 * PAD;
    __nv_bfloat16* WTh = EAl + 128 * PAD;
    __nv_bfloat16* WTl = WTh + 128 * PAD;
    float* g1s  = (float*)(WTl + 128 * PAD);
    float* be1s = g1s + 128;
    int*   sd   = (int*)(be1s + 128);
    int*   dd   = sd + 128;

    int tid = threadIdx.x;
    for (int idx = tid; idx < DE * DO; idx += 256) {
        int k = idx >> 7, o = idx & 127;
        float v = W1a[(DN + k) * DO + o];
        __nv_bfloat16 h = __float2bfloat16(v);
        WTh[o * PAD + k] = h;
        WTl[o * PAD + k] = __float2bfloat16(v - __bfloat162float(h));
    }
    if (tid < 128) {
        g1s [tid] = g1 [tid];
        be1s[tid] = be1[tid];
    }

    uint32_t sEAh = (uint32_t)__cvta_generic_to_shared(EAh);
    uint32_t sEAl = (uint32_t)__cvta_generic_to_shared(EAl);
    uint32_t sWTh = (uint32_t)__cvta_generic_to_shared(WTh);
    uint32_t sWTl = (uint32_t)__cvta_generic_to_shared(WTl);

    int warp = tid >> 5, lane = tid & 31;
    int R  = warp * 16;
    int qr = lane >> 2, qc = lane & 3;

    const float2* g1f2  = (const float2*)g1s;
    const float2* be1f2 = (const float2*)be1s;

    int ntiles = (E + 127) >> 7;
    for (int tile = blockIdx.x; tile < ntiles; tile += gridDim.x) {
        int base = tile << 7;
        __syncthreads();
        {
            int e  = tid >> 1;
            int kb = (tid & 1) * 32;
            int eg = base + e; if (eg >= E) eg = E - 1;
            const float4* s = (const float4*)(ea + (size_t)eg * DE + kb);
            ull* ph = (ull*)(EAh + e * PAD + kb);
            ull* pl = (ull*)(EAl + e * PAD + kb);
#pragma unroll
            for (int j = 0; j < 8; ++j) f4_to_hl(s[j], ph[j], pl[j]);
            if (tid < 128) {
                int eg2 = base + tid; if (eg2 >= E) eg2 = E - 1;
                sd[tid] = ei[eg2];
                dd[tid] = ei[E + eg2];
            }
        }
        __syncthreads();

        float d[16][4];
#pragma unroll
        for (int t = 0; t < 16; ++t) { d[t][0] = d[t][1] = d[t][2] = d[t][3] = 0.f; }
        gemm_hl(sEAh, sEAl, sWTh, sWTl, R, lane, d, 4, PAD);
        __syncthreads();

#pragma unroll
        for (int half = 0; half < 2; ++half) {
            int r   = R + qr + half * 8;
            int src = sd[r], dst = dd[r];
            const float2* bx = (const float2*)(g_xw1 + (size_t)src * DO);

            float sum = 0.f;
#pragma unroll
            for (int t = 0; t < 16; ++t) {
                float2 b = __ldg(bx + t * 4 + qc);
                float v0 = d[t][half * 2 + 0] + b.x;
                float v1 = d[t][half * 2 + 1] + b.y;
                v0 = v0 >= 0.f ? v0 : NEG_SLOPE * v0;
                v1 = v1 >= 0.f ? v1 : NEG_SLOPE * v1;
                d[t][half * 2 + 0] = v0;
                d[t][half * 2 + 1] = v1;
                sum += v0 + v1;
            }
            sum += __shfl_xor_sync(0xffffffffu, sum, 1);
            sum += __shfl_xor_sync(0xffffffffu, sum, 2);
            float mu = sum * (1.0f / DO);

            float vv = 0.f;
#pragma unroll
            for (int t = 0; t < 16; ++t) {
                float e0 = d[t][half * 2 + 0] - mu;
                float e1 = d[t][half * 2 + 1] - mu;
                vv += e0 * e0 + e1 * e1;
            }
            vv += __shfl_xor_sync(0xffffffffu, vv, 1);
            vv += __shfl_xor_sync(0xffffffffu, vv, 2);
            float inv = rsqrtf(vv * (1.0f / DO) + LN_EPS);

            if (base + r < E) {
                float* p = g_sums + (size_t)dst * DO;
#pragma unroll
                for (int t = 0; t < 16; ++t) {
                    float2 gv = g1f2[t * 4 + qc];
                    float2 bv = be1f2[t * 4 + qc];
                    float t0 = (d[t][half * 2 + 0] - mu) * inv * gv.x + bv.x;
                    float t1 = (d[t][half * 2 + 1] - mu) * inv * gv.y + bv.y;
                    asm volatile("red.global.add.v2.f32 [%0], {%1, %2};"
                                 :: "l"(p + t * 8 + qc * 2), "f"(t0), "f"(t1) : "memory");
                }
                if (qc == 0) atomicAdd(g_cnt + dst, 1.0f);
            }
        }
    }
}

// ---------------- kernel 4: fused node MLP via MMA -------------------------
__global__ void __launch_bounds__(256, 1) node_fused(
        const float* __restrict__ W2b,
        const float* __restrict__ g2,
        const float* __restrict__ be2,
        const float* __restrict__ b2b,
        float* __restrict__ out,
        int N) {
    extern __shared__ __align__(16) char smraw[];
    __nv_bfloat16* Th  = (__nv_bfloat16*)smraw;
    __nv_bfloat16* Tl  = Th  + 128 * PAD2;
    __nv_bfloat16* Wch = Tl  + 128 * PAD2;
    __nv_bfloat16* Wcl = Wch + 128 * PAD2;
    __nv_bfloat16* Wbh = Wcl + 128 * PAD2;
    __nv_bfloat16* Wbl = Wbh + 128 * PAD2;
    float* cs   = (float*)(Wbl + 128 * PAD2);
    float* c2s  = cs  + 128;
    float* g2s  = c2s + 128;
    float* be2s = g2s + 128;
    float* b2bs = be2s + 128;

    int tid = threadIdx.x;
    for (int idx = tid; idx < DO * DO; idx += 256) {
        int k = idx >> 7, o = idx & 127;
        float v = g_Wc[idx];
        __nv_bfloat16 h = __float2bfloat16(v);
        Wch[o * PAD2 + k] = h;
        Wcl[o * PAD2 + k] = __float2bfloat16(v - __bfloat162float(h));
        float w = W2b[idx];
        __nv_bfloat16 h2 = __float2bfloat16(w);
        Wbh[o * PAD2 + k] = h2;
        Wbl[o * PAD2 + k] = __float2bfloat16(w - __bfloat162float(h2));
    }
    if (tid < DO) {
        c2s [tid] = g_c2[tid];
        g2s [tid] = g2 [tid];
        be2s[tid] = be2[tid];
        b2bs[tid] = b2b[tid];
    }
    __syncthreads();

    uint32_t sTh  = (uint32_t)__cvta_generic_to_shared(Th);
    uint32_t sTl  = (uint32_t)__cvta_generic_to_shared(Tl);
    uint32_t sWch = (uint32_t)__cvta_generic_to_shared(Wch);
    uint32_t sWcl = (uint32_t)__cvta_generic_to_shared(Wcl);
    uint32_t sWbh = (uint32_t)__cvta_generic_to_shared(Wbh);
    uint32_t sWbl = (uint32_t)__cvta_generic_to_shared(Wbl);

    int warp = tid >> 5, lane = tid & 31;
    int R = warp * 16, qr = lane >> 2, qc = lane & 3;
    const float2* c2f2  = (const float2*)c2s;
    const float2* g2f2  = (const float2*)g2s;
    const float2* be2f2 = (const float2*)be2s;
    const float2* b2bf2 = (const float2*)b2bs;

    int srow = tid >> 1, skb = (tid & 1) * 64;
    int ntiles = (N + 127) >> 7;
    for (int tile = blockIdx.x; tile < ntiles; tile += gridDim.x) {
        int base = tile << 7;
        {
            int node = base + srow; if (node >= N) node = N - 1;
            float cn = g_cnt[node];
            float ic = cn > 0.f ? (1.0f / cn) : 0.f;
            if ((tid & 1) == 0) cs[srow] = cn;
            const float4* s = (const float4*)(g_sums + (size_t)node * DO + skb);
            ull* ph = (ull*)(Th + srow * PAD2 + skb);
            ull* pl = (ull*)(Tl + srow * PAD2 + skb);
#pragma unroll
            for (int j = 0; j < 16; ++j) {
                float4 v = s[j];
                v.x *= ic; v.y *= ic; v.z *= ic; v.w *= ic;
                f4_to_hl(v, ph[j], pl[j]);
            }
        }
        __syncwarp();

        float d[16][4];
#pragma unroll
        for (int t = 0; t < 16; ++t) d[t][0] = d[t][1] = d[t][2] = d[t][3] = 0.f;
        gemm_hl(sTh, sTl, sWch, sWcl, R, lane, d, 8, PAD2);
        __syncwarp();

#pragma unroll
        for (int half = 0; half < 2; ++half) {
            int r = R + qr + half * 8;
            int node = base + r; if (node >= N) node = N - 1;
            float cnr = cs[r];
            const float2* xw = (const float2*)(g_xw2 + (size_t)node * DO);

            float sum = 0.f;
#pragma unroll
            for (int t = 0; t < 16; ++t) {
                float2 b  = __ldg(xw + t * 4 + qc);
                float2 cv = c2f2[t * 4 + qc];
                float add0 = cnr > 0.f ? cv.x : 0.f;
                float add1 = cnr > 0.f ? cv.y : 0.f;
                float v0 = d[t][half * 2 + 0] + b.x + add0;
                float v1 = d[t][half * 2 + 1] + b.y + add1;
                v0 = v0 >= 0.f ? v0 : NEG_SLOPE * v0;
                v1 = v1 >= 0.f ? v1 : NEG_SLOPE * v1;
                d[t][half * 2 + 0] = v0;
                d[t][half * 2 + 1] = v1;
                sum += v0 + v1;
            }
            sum += __shfl_xor_sync(0xffffffffu, sum, 1);
            sum += __shfl_xor_sync(0xffffffffu, sum, 2);
            float mu = sum * (1.0f / DO);

            float vv = 0.f;
#pragma unroll
            for (int t = 0; t < 16; ++t) {
                float e0 = d[t][half * 2 + 0] - mu;
                float e1 = d[t][half * 2 + 1] - mu;
                vv += e0 * e0 + e1 * e1;
            }
            vv += __shfl_xor_sync(0xffffffffu, vv, 1);
            vv += __shfl_xor_sync(0xffffffffu, vv, 2);
            float inv = rsqrtf(vv * (1.0f / DO) + LN_EPS);

#pragma unroll
            for (int t = 0; t < 16; ++t) {
                float2 gv = g2f2[t * 4 + qc];
                float2 bv = be2f2[t * 4 + qc];
                float t0 = (d[t][half * 2 + 0] - mu) * inv * gv.x + bv.x;
                float t1 = (d[t][half * 2 + 1] - mu) * inv * gv.y + bv.y;
                __nv_bfloat16 h0 = __float2bfloat16(t0);
                __nv_bfloat16 h1 = __float2bfloat16(t1);
                int off = r * PAD2 + t * 8 + 2 * qc;
                *(uint32_t*)(Th + off) = bfpair(t0, t1);
                *(uint32_t*)(Tl + off) = bfpair(t0 - __bfloat162float(h0),
                                                t1 - __bfloat162float(h1));
            }
        }
        __syncwarp();

#pragma unroll
        for (int t = 0; t < 16; ++t) d[t][0] = d[t][1] = d[t][2] = d[t][3] = 0.f;
        gemm_hl(sTh, sTl, sWbh, sWbl, R, lane, d, 8, PAD2);

#pragma unroll
        for (int half = 0; half < 2; ++half) {
            int node = base + R + qr + half * 8;
            if (node < N) {
                float2* o = (float2*)(out + (size_t)node * DO);
#pragma unroll
                for (int t = 0; t < 16; ++t) {
                    float2 b = b2bf2[t * 4 + qc];
                    o[t * 4 + qc] = make_float2(d[t][half * 2] + b.x,
                                                d[t][half * 2 + 1] + b.y);
                }
            }
        }
        __syncwarp();
    }
}

// ---------------- launcher -------------------------------------------------
static bool g_attr_done = false;

extern "C" void kernel_launch(void* const* d_in, const int* in_sizes, int n_in,
                              void* d_out, int out_size) {
    const float* x   = (const float*)d_in[0];
    const int*   ei  = (const int*)  d_in[1];
    const float* ea  = (const float*)d_in[2];
    const float* u   = (const float*)d_in[3];
    const float* W1a = (const float*)d_in[5];
    const float* b1a = (const float*)d_in[6];
    const float* g1  = (const float*)d_in[7];
    const float* be1 = (const float*)d_in[8];
    const float* W1b = (const float*)d_in[9];
    const float* b1b = (const float*)d_in[10];
    const float* W2a = (const float*)d_in[11];
    const float* b2a = (const float*)d_in[12];
    const float* g2  = (const float*)d_in[13];
    const float* be2 = (const float*)d_in[14];
    const float* W2b = (const float*)d_in[15];
    const float* b2b = (const float*)d_in[16];
    float* out = (float*)d_out;

    int N = in_sizes[0] / DN;
    int E = in_sizes[2] / DE;

    const int PRE2_SMEM = 6 * 128 * PAD2 * 2 + 2 * 128 * 4;                // 209536
    const int EDGE_SMEM = 4 * 128 * PAD * 2 + 2 * 128 * 4 + 2 * 128 * 4;   // 75776
    const int NF_SMEM   = 6 * 128 * PAD2 * 2 + 5 * 128 * 4;                // 211456

    if (!g_attr_done) {
        cudaFuncSetAttribute(precompute_mma, cudaFuncAttributeMaxDynamicSharedMemorySize, PRE2_SMEM);
        cudaFuncSetAttribute(edge_kernel,    cudaFuncAttributeMaxDynamicSharedMemorySize, EDGE_SMEM);
        cudaFuncSetAttribute(node_fused,     cudaFuncAttributeMaxDynamicSharedMemorySize, NF_SMEM);
        g_attr_done = true;
    }

    c1_kernel<<<1, 128>>>(W1a, b1a, u);
    wc_kernel<<<129, 128>>>(W1b, b1b, W2a);
    zero_kernel<<<256, 256>>>(N * DO, N);
    precompute_mma<<<148, 256, PRE2_SMEM>>>(x, W1a, W2a, b2a, N);
    edge_kernel<<<296, 256, EDGE_SMEM>>>(ei, ea, W1a, g1, be1, E);
    node_fused<<<148, 256, NF_SMEM>>>(W2b, g2, be2, b2b, out, N);
}